// round 5
// baseline (speedup 1.0000x reference)
#include <cuda_runtime.h>
#include <math.h>
#include <cstdint>

#define BB   4
#define SS   2048
#define DIMC 2048
#define NH   16
#define NKV  4
#define HD   128
#define QKVC 3072
#define EPSF 1.1920928955078125e-07f
#define NEGF -1e30f

// Scratch (device globals: allocation-free per harness rules)
__device__ float g_qkv[(size_t)BB * SS * QKVC];   // 96 MB
__device__ float g_attn[(size_t)BB * SS * DIMC];  // 64 MB
__device__ unsigned char g_mask[BB * SS];         // canonical 0/1 mask

// ===========================================================================
// Portable helpers (sm_80-baseline ISA only; NO 'a'-suffix features)
// ===========================================================================
__device__ __forceinline__ uint32_t smem_u32(const void* p) {
    uint32_t a;
    asm("{ .reg .u64 t; cvta.to.shared.u64 t, %1; cvt.u32.u64 %0, t; }" : "=r"(a) : "l"(p));
    return a;
}
__device__ __forceinline__ void cp16(uint32_t s, const void* g) {
    asm volatile("cp.async.cg.shared.global [%0], [%1], 16;" :: "r"(s), "l"(g));
}
#define CP_COMMIT() asm volatile("cp.async.commit_group;" ::: "memory")
#define CP_WAIT(n)  asm volatile("cp.async.wait_group %0;" :: "n"(n) : "memory")

__device__ __forceinline__ uint32_t f2tf32(float f) {
    uint32_t r;
    asm("cvt.rna.tf32.f32 %0, %1;" : "=r"(r) : "f"(f));
    return r;
}
__device__ __forceinline__ void mma_tf32(float* c, uint32_t a0, uint32_t a1,
                                         uint32_t a2, uint32_t a3,
                                         uint32_t b0, uint32_t b1) {
    asm volatile(
        "mma.sync.aligned.m16n8k8.row.col.f32.tf32.tf32.f32 "
        "{%0,%1,%2,%3}, {%4,%5,%6,%7}, {%8,%9}, {%0,%1,%2,%3};"
        : "+f"(c[0]), "+f"(c[1]), "+f"(c[2]), "+f"(c[3])
        : "r"(a0), "r"(a1), "r"(a2), "r"(a3), "r"(b0), "r"(b1));
}

// ===========================================================================
// Mask canonicalization (dtype-robust): writes 0/1 bytes into g_mask.
// ===========================================================================
__global__ __launch_bounds__(256) void mask_prep(const unsigned char* __restrict__ raw)
{
    __shared__ int kind;  // 0=int32, 1=bool/u8, 2=float32
    if (threadIdx.x == 0) kind = 0;
    __syncthreads();
    const int NTOK = BB * SS;
    for (int i = threadIdx.x; i < NTOK; i += 256) {
        unsigned char v = raw[i];
        if ((i & 3) == 3 && v == 0x3F) kind = 2;
        else if ((i & 3) != 0 && v != 0) kind = 1;
    }
    __syncthreads();
    int k = kind;
    for (int i = threadIdx.x; i < NTOK; i += 256) {
        unsigned char m;
        if (k == 2)      m = (((const float*)raw)[i] != 0.0f);
        else if (k == 1) m = (raw[i] != 0);
        else             m = (((const int*)raw)[i] != 0);
        g_mask[i] = m;
    }
}

// ===========================================================================
// TF32 mma.sync GEMM: C[M,N] = A[M,K] * B[N,K]^T.
// CTA 128x128, K-tile 32, 3-stage cp.async pipeline, 8 warps (2x4 grid),
// warp tile 64x32 = 4x4 m16n8k8 fragments. Smem row stride 36 floats
// (conflict-free fragment loads, 144B = 16B-aligned rows).
// ===========================================================================
#define AROW    36
#define TILEF   (128 * AROW)          // floats per operand tile
#define STAGEF  (2 * TILEF)           // floats per stage (A+B)
#define GSTAGES 3
#define GEMM_SMEM (GSTAGES * STAGEF * 4)   // 110592 B

__device__ __forceinline__ void ld_stage(uint32_t sA, uint32_t sB,
                                         const float* gA, const float* gB,
                                         int K, int kof, int t)
{
    const int q = t & 7;          // 16B quad within 32-float row
    const int r0 = t >> 3;        // 0..31
#pragma unroll
    for (int i = 0; i < 4; i++) {
        const int r = r0 + 32 * i;
        const uint32_t soff = (uint32_t)(r * AROW + q * 4) * 4u;
        cp16(sA + soff, gA + (size_t)r * K + kof + q * 4);
        cp16(sB + soff, gB + (size_t)r * K + kof + q * 4);
    }
}

__global__ __launch_bounds__(256) void gemm_mma(const float* __restrict__ A,
                                                const float* __restrict__ Bm,
                                                float* __restrict__ C,
                                                int M, int N, int K)
{
    extern __shared__ __align__(16) float sm[];
    const uint32_t smb = smem_u32(sm);
    const int t = threadIdx.x;
    const int lane = t & 31;
    const int wid = t >> 5;
    const int wr = wid >> 2;      // 0..1 : 64 rows each
    const int wc = wid & 3;       // 0..3 : 32 cols each
    const int g = lane >> 2;      // 0..7
    const int q = lane & 3;       // 0..3
    const int m0 = blockIdx.y * 128;
    const int n0 = blockIdx.x * 128;
    const int NK = K >> 5;

    const float* gA = A + (size_t)m0 * K;
    const float* gB = Bm + (size_t)n0 * K;

    float c[4][4][4];
#pragma unroll
    for (int i = 0; i < 4; i++)
#pragma unroll
        for (int j = 0; j < 4; j++)
#pragma unroll
            for (int r = 0; r < 4; r++) c[i][j][r] = 0.f;

    // Prologue: stages 0,1
#pragma unroll
    for (int s = 0; s < 2; s++) {
        uint32_t sb = smb + s * STAGEF * 4;
        ld_stage(sb, sb + TILEF * 4, gA, gB, K, s * 32, t);
        CP_COMMIT();
    }

    for (int kt = 0; kt < NK; kt++) {
        CP_WAIT(1);
        __syncthreads();

        const float* As = sm + (kt % 3) * STAGEF;
        const float* Bs = As + TILEF;
        const float* Aw = As + (wr * 64) * AROW;
        const float* Bw = Bs + (wc * 32) * AROW;

#pragma unroll
        for (int ks = 0; ks < 4; ks++) {
            const int k0 = ks * 8;
            uint32_t bf[4][2];
#pragma unroll
            for (int j = 0; j < 4; j++) {
                bf[j][0] = f2tf32(Bw[(j * 8 + g) * AROW + k0 + q]);
                bf[j][1] = f2tf32(Bw[(j * 8 + g) * AROW + k0 + 4 + q]);
            }
#pragma unroll
            for (int i = 0; i < 4; i++) {
                uint32_t a0 = f2tf32(Aw[(i * 16 + g) * AROW + k0 + q]);
                uint32_t a1 = f2tf32(Aw[(i * 16 + 8 + g) * AROW + k0 + q]);
                uint32_t a2 = f2tf32(Aw[(i * 16 + g) * AROW + k0 + 4 + q]);
                uint32_t a3 = f2tf32(Aw[(i * 16 + 8 + g) * AROW + k0 + 4 + q]);
#pragma unroll
                for (int j = 0; j < 4; j++)
                    mma_tf32(c[i][j], a0, a1, a2, a3, bf[j][0], bf[j][1]);
            }
        }

        // Prefetch stage kt+2 (always commit a group to keep FIFO depth fixed)
        const int pf = kt + 2;
        if (pf < NK) {
            uint32_t sb = smb + (pf % 3) * STAGEF * 4;
            ld_stage(sb, sb + TILEF * 4, gA, gB, K, pf * 32, t);
        }
        CP_COMMIT();
    }

    // Epilogue: write C
#pragma unroll
    for (int i = 0; i < 4; i++) {
        const int row = m0 + wr * 64 + i * 16 + g;
#pragma unroll
        for (int j = 0; j < 4; j++) {
            const int col = n0 + wc * 32 + j * 8 + q * 2;
            *(float2*)(C + (size_t)row * N + col) = make_float2(c[i][j][0], c[i][j][1]);
            *(float2*)(C + (size_t)(row + 8) * N + col) = make_float2(c[i][j][2], c[i][j][3]);
        }
    }
}

// ===========================================================================
// Fused per-head RMSNorm + interleaved RoPE (in-place on qkv buffer).
// ===========================================================================
__global__ __launch_bounds__(128) void norm_rope_kernel(float* __restrict__ qkv,
                                                        const float* __restrict__ qw,
                                                        const float* __restrict__ kw,
                                                        const float* __restrict__ fcos,
                                                        const float* __restrict__ fsin)
{
    const int head = blockIdx.x;
    const int s    = blockIdx.y;
    const int b    = blockIdx.z;
    const int t    = threadIdx.x;

    const size_t rowbase = ((size_t)(b * SS + s)) * QKVC;
    const int off = (head < NH) ? head * HD : DIMC + (head - NH) * HD;
    const float* w = (head < NH) ? qw : kw;

    float x = qkv[rowbase + off + t];

    float ssum = x * x;
#pragma unroll
    for (int o = 16; o > 0; o >>= 1) ssum += __shfl_xor_sync(0xffffffffu, ssum, o);
    __shared__ float red[4];
    if ((t & 31) == 0) red[t >> 5] = ssum;
    __syncthreads();
    float tot = red[0] + red[1] + red[2] + red[3];
    float r = rsqrtf(tot * (1.f / HD) + EPSF);

    float xn = x * r * w[t];
    float partner = __shfl_xor_sync(0xffffffffu, xn, 1);
    float rot = (t & 1) ? partner : -partner;
    float c = fcos[s * HD + t];
    float sn = fsin[s * HD + t];
    qkv[rowbase + off + t] = xn * c + rot * sn;
}

// ===========================================================================
// Flash-style GQA attention (fp32 SIMT, proven-correct version).
// ===========================================================================
#define ATT_SMEM_FLOATS (8192 * 3 + 64 * 65 + 64)
#define ATT_SMEM_BYTES  (ATT_SMEM_FLOATS * 4)

__global__ __launch_bounds__(256) void attn_kernel(const float* __restrict__ qkv,
                                                   const unsigned char* __restrict__ vis,
                                                   float* __restrict__ outp)
{
    extern __shared__ float smf[];
    float* Qs = smf;
    float* Ks = Qs + 8192;
    float* Vs = Ks + 8192;
    float* Ps = Vs + 8192;
    float* sv = Ps + 64 * 65;

    const int qt = blockIdx.x;
    const int h  = blockIdx.y;
    const int b  = blockIdx.z;
    const int kvh = h >> 2;
    const int t  = threadIdx.x;
    const int ty = t >> 4;
    const int tx = t & 15;

    const size_t tokbase = (size_t)b * SS;
    const float* Qg = qkv + (tokbase + qt * 64) * QKVC + h * HD;
    const unsigned char* visb = vis + tokbase;

    for (int idx = t; idx < 64 * 32; idx += 256) {
        int row = idx >> 5, d4 = idx & 31;
        float4 v = *(const float4*)(Qg + (size_t)row * QKVC + d4 * 4);
        int c4 = (row >> 2) ^ (d4 & 15);
        int pb = (d4 << 8) + (c4 << 2) + (row & 3);
        Qs[pb] = v.x; Qs[pb + 64] = v.y; Qs[pb + 128] = v.z; Qs[pb + 192] = v.w;
    }

    float m_i[4], l_i[4], o[4][8];
#pragma unroll
    for (int i = 0; i < 4; i++) {
        m_i[i] = -INFINITY; l_i[i] = 0.f;
#pragma unroll
        for (int j = 0; j < 8; j++) o[i][j] = 0.f;
    }
    const float scale = 0.08838834764831843f;

    for (int kt = 0; kt < SS / 64; kt++) {
        __syncthreads();
        const float* Kg = qkv + (tokbase + kt * 64) * QKVC + DIMC + kvh * HD;
        const float* Vg = Kg + NKV * HD;
        for (int idx = t; idx < 64 * 32; idx += 256) {
            int row = idx >> 5, d4 = idx & 31;
            float4 kv4 = *(const float4*)(Kg + (size_t)row * QKVC + d4 * 4);
            int c4 = (row >> 2) ^ (d4 & 15);
            int pb = (d4 << 8) + (c4 << 2) + (row & 3);
            Ks[pb] = kv4.x; Ks[pb + 64] = kv4.y; Ks[pb + 128] = kv4.z; Ks[pb + 192] = kv4.w;
            float4 vv4 = *(const float4*)(Vg + (size_t)row * QKVC + d4 * 4);
            *(float4*)(Vs + (row << 7) + (d4 << 2)) = vv4;
        }
        if (t < 64) sv[t] = visb[kt * 64 + t] ? 0.f : NEGF;
        __syncthreads();

        float s4[4][4];
#pragma unroll
        for (int i = 0; i < 4; i++)
#pragma unroll
            for (int j = 0; j < 4; j++) s4[i][j] = 0.f;

#pragma unroll 4
        for (int d = 0; d < 128; d++) {
            int sw = (d >> 2) & 15;
            float4 aq = *(const float4*)&Qs[(d << 6) + ((ty ^ sw) << 2)];
            float4 bk = *(const float4*)&Ks[(d << 6) + ((tx ^ sw) << 2)];
            float a[4] = {aq.x, aq.y, aq.z, aq.w};
            float bb2[4] = {bk.x, bk.y, bk.z, bk.w};
#pragma unroll
            for (int i = 0; i < 4; i++)
#pragma unroll
                for (int j = 0; j < 4; j++) s4[i][j] += a[i] * bb2[j];
        }

        float addm[4];
#pragma unroll
        for (int j = 0; j < 4; j++) addm[j] = sv[tx * 4 + j];

        float alpha[4];
#pragma unroll
        for (int i = 0; i < 4; i++) {
            float rmax = -INFINITY;
#pragma unroll
            for (int j = 0; j < 4; j++) {
                s4[i][j] = s4[i][j] * scale + addm[j];
                rmax = fmaxf(rmax, s4[i][j]);
            }
#pragma unroll
            for (int off = 8; off > 0; off >>= 1)
                rmax = fmaxf(rmax, __shfl_xor_sync(0xffffffffu, rmax, off));
            float mn = fmaxf(m_i[i], rmax);
            float ps = 0.f;
#pragma unroll
            for (int j = 0; j < 4; j++) {
                float p = __expf(s4[i][j] - mn);
                s4[i][j] = p;
                ps += p;
            }
#pragma unroll
            for (int off = 8; off > 0; off >>= 1)
                ps += __shfl_xor_sync(0xffffffffu, ps, off);
            float al = __expf(m_i[i] - mn);
            l_i[i] = l_i[i] * al + ps;
            m_i[i] = mn;
            alpha[i] = al;
#pragma unroll
            for (int j = 0; j < 4; j++)
                Ps[(ty * 4 + i) * 65 + tx * 4 + j] = s4[i][j];
        }
        __syncthreads();

#pragma unroll
        for (int i = 0; i < 4; i++)
#pragma unroll
            for (int j = 0; j < 8; j++) o[i][j] *= alpha[i];

#pragma unroll 2
        for (int kk = 0; kk < 64; kk++) {
            float4 v0 = *(const float4*)&Vs[(kk << 7) + (tx << 2)];
            float4 v1 = *(const float4*)&Vs[(kk << 7) + 64 + (tx << 2)];
#pragma unroll
            for (int i = 0; i < 4; i++) {
                float p = Ps[(ty * 4 + i) * 65 + kk];
                o[i][0] += p * v0.x; o[i][1] += p * v0.y;
                o[i][2] += p * v0.z; o[i][3] += p * v0.w;
                o[i][4] += p * v1.x; o[i][5] += p * v1.y;
                o[i][6] += p * v1.z; o[i][7] += p * v1.w;
            }
        }
    }

#pragma unroll
    for (int i = 0; i < 4; i++) {
        int row = qt * 64 + ty * 4 + i;
        float f = visb[row] ? (1.f / l_i[i]) : 0.f;
        float* op = outp + (tokbase + row) * DIMC + h * HD;
        float4 w0 = make_float4(o[i][0] * f, o[i][1] * f, o[i][2] * f, o[i][3] * f);
        float4 w1 = make_float4(o[i][4] * f, o[i][5] * f, o[i][6] * f, o[i][7] * f);
        *(float4*)(op + tx * 4) = w0;
        *(float4*)(op + 64 + tx * 4) = w1;
    }
}

// ---------------------------------------------------------------------------
extern "C" void kernel_launch(void* const* d_in, const int* in_sizes, int n_in,
                              void* d_out, int out_size)
{
    const float* x    = (const float*)d_in[0];
    const float* wqkv = (const float*)d_in[1];
    const float* wo   = (const float*)d_in[2];
    const float* qw   = (const float*)d_in[3];
    const float* kw   = (const float*)d_in[4];
    const float* fc   = (const float*)d_in[5];
    const float* fs   = (const float*)d_in[6];
    const unsigned char* visraw = (const unsigned char*)d_in[7];
    float* out = (float*)d_out;

    float *qkv, *attn;
    unsigned char* mask;
    cudaGetSymbolAddress((void**)&qkv, g_qkv);
    cudaGetSymbolAddress((void**)&attn, g_attn);
    cudaGetSymbolAddress((void**)&mask, g_mask);

    // 0) Canonicalize visibility mask
    mask_prep<<<1, 256>>>(visraw);

    // 1) QKV projection (tf32 mma.sync): [8192,2048] x [3072,2048]^T
    cudaFuncSetAttribute(gemm_mma, cudaFuncAttributeMaxDynamicSharedMemorySize, GEMM_SMEM);
    gemm_mma<<<dim3(QKVC / 128, (BB * SS) / 128), 256, GEMM_SMEM>>>(
        x, wqkv, qkv, BB * SS, QKVC, DIMC);

    // 2) RMSNorm + RoPE on q & k heads (in place)
    norm_rope_kernel<<<dim3(NH + NKV, SS, BB), 128>>>(qkv, qw, kw, fc, fs);

    // 3) Attention (fp32 SIMT flash)
    cudaFuncSetAttribute(attn_kernel, cudaFuncAttributeMaxDynamicSharedMemorySize,
                         ATT_SMEM_BYTES);
    attn_kernel<<<dim3(SS / 64, NH, BB), 256, ATT_SMEM_BYTES>>>(qkv, mask, attn);

    // 4) Output projection (tf32 mma.sync): [8192,2048] x [2048,2048]^T
    gemm_mma<<<dim3(DIMC / 128, (BB * SS) / 128), 256, GEMM_SMEM>>>(
        attn, wo, out, BB * SS, DIMC, DIMC);
}

// round 8
// speedup vs baseline: 1.9358x; 1.9358x over previous
#include <cuda_runtime.h>
#include <math.h>
#include <cstdint>

#define BB   4
#define SS   2048
#define DIMC 2048
#define NH   16
#define NKV  4
#define HD   128
#define QKVC 3072
#define EPSF 1.1920928955078125e-07f
#define NEGF -1e30f

// Scratch (device globals: allocation-free per harness rules)
__device__ float g_qkv[(size_t)BB * SS * QKVC];   // 96 MB
__device__ float g_attn[(size_t)BB * SS * DIMC];  // 64 MB  (tf32-rounded by attn)
__device__ float g_xr[(size_t)BB * SS * DIMC];    // 64 MB  x rounded to tf32
__device__ float g_wqr[(size_t)QKVC * DIMC];      // 24 MB  wqkv rounded
__device__ float g_wor[(size_t)DIMC * DIMC];      // 16 MB  wo rounded
__device__ unsigned char g_mask[BB * SS];         // canonical 0/1 mask

// ===========================================================================
// Portable helpers (sm_80-baseline ISA only; NO 'a'-suffix features)
// ===========================================================================
__device__ __forceinline__ uint32_t smem_u32(const void* p) {
    uint32_t a;
    asm("{ .reg .u64 t; cvta.to.shared.u64 t, %1; cvt.u32.u64 %0, t; }" : "=r"(a) : "l"(p));
    return a;
}
__device__ __forceinline__ void cp16(uint32_t s, const void* g) {
    asm volatile("cp.async.cg.shared.global [%0], [%1], 16;" :: "r"(s), "l"(g));
}
#define CP_COMMIT() asm volatile("cp.async.commit_group;" ::: "memory")
#define CP_WAIT(n)  asm volatile("cp.async.wait_group %0;" :: "n"(n) : "memory")

__device__ __forceinline__ uint32_t f2tf32(float f) {
    uint32_t r;
    asm("cvt.rna.tf32.f32 %0, %1;" : "=r"(r) : "f"(f));
    return r;
}
__device__ __forceinline__ void mma_tf32(float* c, uint32_t a0, uint32_t a1,
                                         uint32_t a2, uint32_t a3,
                                         uint32_t b0, uint32_t b1) {
    asm volatile(
        "mma.sync.aligned.m16n8k8.row.col.f32.tf32.tf32.f32 "
        "{%0,%1,%2,%3}, {%4,%5,%6,%7}, {%8,%9}, {%0,%1,%2,%3};"
        : "+f"(c[0]), "+f"(c[1]), "+f"(c[2]), "+f"(c[3])
        : "r"(a0), "r"(a1), "r"(a2), "r"(a3), "r"(b0), "r"(b1));
}

// ===========================================================================
// Elementwise tf32 pre-round: out[i] = rna_tf32(in[i]) as f32 bits.
// ===========================================================================
__global__ __launch_bounds__(256) void round_tf32(const float4* __restrict__ in,
                                                  float4* __restrict__ out, int n4)
{
    for (int i = blockIdx.x * 256 + threadIdx.x; i < n4; i += gridDim.x * 256) {
        float4 v = in[i];
        v.x = __uint_as_float(f2tf32(v.x));
        v.y = __uint_as_float(f2tf32(v.y));
        v.z = __uint_as_float(f2tf32(v.z));
        v.w = __uint_as_float(f2tf32(v.w));
        out[i] = v;
    }
}

// ===========================================================================
// Mask canonicalization (dtype-robust): writes 0/1 bytes into g_mask.
// ===========================================================================
__global__ __launch_bounds__(256) void mask_prep(const unsigned char* __restrict__ raw)
{
    __shared__ int kind;  // 0=int32, 1=bool/u8, 2=float32
    if (threadIdx.x == 0) kind = 0;
    __syncthreads();
    const int NTOK = BB * SS;
    for (int i = threadIdx.x; i < NTOK; i += 256) {
        unsigned char v = raw[i];
        if ((i & 3) == 3 && v == 0x3F) kind = 2;
        else if ((i & 3) != 0 && v != 0) kind = 1;
    }
    __syncthreads();
    int k = kind;
    for (int i = threadIdx.x; i < NTOK; i += 256) {
        unsigned char m;
        if (k == 2)      m = (((const float*)raw)[i] != 0.0f);
        else if (k == 1) m = (raw[i] != 0);
        else             m = (((const int*)raw)[i] != 0);
        g_mask[i] = m;
    }
}

// ===========================================================================
// TF32 mma.sync GEMM: C[M,N] = A[M,K] * B[N,K]^T.  Inputs PRE-ROUNDED to
// tf32 bits, so fragments are raw smem loads (no cvt in hot loop).
// CTA 128x128, K-tile 32, 3-stage cp.async, 8 warps (2x4), warp 64x32.
// __launch_bounds__(256,2): 2 CTAs/SM (221KB smem of 228KB).
// ===========================================================================
#define AROW    36
#define TILEF   (128 * AROW)
#define STAGEF  (2 * TILEF)
#define GSTAGES 3
#define GEMM_SMEM (GSTAGES * STAGEF * 4)   // 110592 B

__device__ __forceinline__ void ld_stage(uint32_t sA, uint32_t sB,
                                         const float* gA, const float* gB,
                                         int K, int kof, int t)
{
    const int q = t & 7;
    const int r0 = t >> 3;
#pragma unroll
    for (int i = 0; i < 4; i++) {
        const int r = r0 + 32 * i;
        const uint32_t soff = (uint32_t)(r * AROW + q * 4) * 4u;
        cp16(sA + soff, gA + (size_t)r * K + kof + q * 4);
        cp16(sB + soff, gB + (size_t)r * K + kof + q * 4);
    }
}

__global__ __launch_bounds__(256, 2) void gemm_mma(const float* __restrict__ A,
                                                   const float* __restrict__ Bm,
                                                   float* __restrict__ C,
                                                   int M, int N, int K)
{
    extern __shared__ __align__(16) float sm[];
    const int t = threadIdx.x;
    const int lane = t & 31;
    const int wid = t >> 5;
    const int wr = wid >> 2;
    const int wc = wid & 3;
    const int g = lane >> 2;
    const int q = lane & 3;
    const int m0 = blockIdx.y * 128;
    const int n0 = blockIdx.x * 128;
    const int NK = K >> 5;
    const uint32_t smb = smem_u32(sm);

    const float* gA = A + (size_t)m0 * K;
    const float* gB = Bm + (size_t)n0 * K;

    float c[4][4][4];
#pragma unroll
    for (int i = 0; i < 4; i++)
#pragma unroll
        for (int j = 0; j < 4; j++)
#pragma unroll
            for (int r = 0; r < 4; r++) c[i][j][r] = 0.f;

#pragma unroll
    for (int s = 0; s < 2; s++) {
        uint32_t sb = smb + s * STAGEF * 4;
        ld_stage(sb, sb + TILEF * 4, gA, gB, K, s * 32, t);
        CP_COMMIT();
    }

    for (int kt = 0; kt < NK; kt++) {
        CP_WAIT(1);
        __syncthreads();

        const uint32_t* As = (const uint32_t*)(sm + (kt % 3) * STAGEF);
        const uint32_t* Aw = As + (wr * 64) * AROW;
        const uint32_t* Bw = As + TILEF + (wc * 32) * AROW;

#pragma unroll
        for (int ks = 0; ks < 4; ks++) {
            const int k0 = ks * 8;
            uint32_t bf[4][2];
#pragma unroll
            for (int j = 0; j < 4; j++) {
                bf[j][0] = Bw[(j * 8 + g) * AROW + k0 + q];
                bf[j][1] = Bw[(j * 8 + g) * AROW + k0 + 4 + q];
            }
#pragma unroll
            for (int i = 0; i < 4; i++) {
                uint32_t a0 = Aw[(i * 16 + g) * AROW + k0 + q];
                uint32_t a1 = Aw[(i * 16 + 8 + g) * AROW + k0 + q];
                uint32_t a2 = Aw[(i * 16 + g) * AROW + k0 + 4 + q];
                uint32_t a3 = Aw[(i * 16 + 8 + g) * AROW + k0 + 4 + q];
#pragma unroll
                for (int j = 0; j < 4; j++)
                    mma_tf32(c[i][j], a0, a1, a2, a3, bf[j][0], bf[j][1]);
            }
        }

        const int pf = kt + 2;
        if (pf < NK) {
            uint32_t sb = smb + (pf % 3) * STAGEF * 4;
            ld_stage(sb, sb + TILEF * 4, gA, gB, K, pf * 32, t);
        }
        CP_COMMIT();
    }

#pragma unroll
    for (int i = 0; i < 4; i++) {
        const int row = m0 + wr * 64 + i * 16 + g;
#pragma unroll
        for (int j = 0; j < 4; j++) {
            const int col = n0 + wc * 32 + j * 8 + q * 2;
            *(float2*)(C + (size_t)row * N + col) = make_float2(c[i][j][0], c[i][j][1]);
            *(float2*)(C + (size_t)(row + 8) * N + col) = make_float2(c[i][j][2], c[i][j][3]);
        }
    }
}

// ===========================================================================
// Fused per-head RMSNorm + interleaved RoPE (in-place on qkv buffer).
// ===========================================================================
__global__ __launch_bounds__(128) void norm_rope_kernel(float* __restrict__ qkv,
                                                        const float* __restrict__ qw,
                                                        const float* __restrict__ kw,
                                                        const float* __restrict__ fcos,
                                                        const float* __restrict__ fsin)
{
    const int head = blockIdx.x;
    const int s    = blockIdx.y;
    const int b    = blockIdx.z;
    const int t    = threadIdx.x;

    const size_t rowbase = ((size_t)(b * SS + s)) * QKVC;
    const int off = (head < NH) ? head * HD : DIMC + (head - NH) * HD;
    const float* w = (head < NH) ? qw : kw;

    float x = qkv[rowbase + off + t];

    float ssum = x * x;
#pragma unroll
    for (int o = 16; o > 0; o >>= 1) ssum += __shfl_xor_sync(0xffffffffu, ssum, o);
    __shared__ float red[4];
    if ((t & 31) == 0) red[t >> 5] = ssum;
    __syncthreads();
    float tot = red[0] + red[1] + red[2] + red[3];
    float r = rsqrtf(tot * (1.f / HD) + EPSF);

    float xn = x * r * w[t];
    float partner = __shfl_xor_sync(0xffffffffu, xn, 1);
    float rot = (t & 1) ? partner : -partner;
    float c = fcos[s * HD + t];
    float sn = fsin[s * HD + t];
    qkv[rowbase + off + t] = xn * c + rot * sn;
}

// ===========================================================================
// Flash-style GQA attention (fp32 SIMT). Epilogue rounds output to tf32 bits
// so the out-projection GEMM needs no cvt.
// ===========================================================================
#define ATT_SMEM_FLOATS (8192 * 3 + 64 * 65 + 64)
#define ATT_SMEM_BYTES  (ATT_SMEM_FLOATS * 4)

__global__ __launch_bounds__(256) void attn_kernel(const float* __restrict__ qkv,
                                                   const unsigned char* __restrict__ vis,
                                                   float* __restrict__ outp)
{
    extern __shared__ float smf[];
    float* Qs = smf;
    float* Ks = Qs + 8192;
    float* Vs = Ks + 8192;
    float* Ps = Vs + 8192;
    float* sv = Ps + 64 * 65;

    const int qt = blockIdx.x;
    const int h  = blockIdx.y;
    const int b  = blockIdx.z;
    const int kvh = h >> 2;
    const int t  = threadIdx.x;
    const int ty = t >> 4;
    const int tx = t & 15;

    const size_t tokbase = (size_t)b * SS;
    const float* Qg = qkv + (tokbase + qt * 64) * QKVC + h * HD;
    const unsigned char* visb = vis + tokbase;

    for (int idx = t; idx < 64 * 32; idx += 256) {
        int row = idx >> 5, d4 = idx & 31;
        float4 v = *(const float4*)(Qg + (size_t)row * QKVC + d4 * 4);
        int c4 = (row >> 2) ^ (d4 & 15);
        int pb = (d4 << 8) + (c4 << 2) + (row & 3);
        Qs[pb] = v.x; Qs[pb + 64] = v.y; Qs[pb + 128] = v.z; Qs[pb + 192] = v.w;
    }

    float m_i[4], l_i[4], o[4][8];
#pragma unroll
    for (int i = 0; i < 4; i++) {
        m_i[i] = -INFINITY; l_i[i] = 0.f;
#pragma unroll
        for (int j = 0; j < 8; j++) o[i][j] = 0.f;
    }
    const float scale = 0.08838834764831843f;

    for (int kt = 0; kt < SS / 64; kt++) {
        __syncthreads();
        const float* Kg = qkv + (tokbase + kt * 64) * QKVC + DIMC + kvh * HD;
        const float* Vg = Kg + NKV * HD;
        for (int idx = t; idx < 64 * 32; idx += 256) {
            int row = idx >> 5, d4 = idx & 31;
            float4 kv4 = *(const float4*)(Kg + (size_t)row * QKVC + d4 * 4);
            int c4 = (row >> 2) ^ (d4 & 15);
            int pb = (d4 << 8) + (c4 << 2) + (row & 3);
            Ks[pb] = kv4.x; Ks[pb + 64] = kv4.y; Ks[pb + 128] = kv4.z; Ks[pb + 192] = kv4.w;
            float4 vv4 = *(const float4*)(Vg + (size_t)row * QKVC + d4 * 4);
            *(float4*)(Vs + (row << 7) + (d4 << 2)) = vv4;
        }
        if (t < 64) sv[t] = visb[kt * 64 + t] ? 0.f : NEGF;
        __syncthreads();

        float s4[4][4];
#pragma unroll
        for (int i = 0; i < 4; i++)
#pragma unroll
            for (int j = 0; j < 4; j++) s4[i][j] = 0.f;

#pragma unroll 4
        for (int d = 0; d < 128; d++) {
            int sw = (d >> 2) & 15;
            float4 aq = *(const float4*)&Qs[(d << 6) + ((ty ^ sw) << 2)];
            float4 bk = *(const float4*)&Ks[(d << 6) + ((tx ^ sw) << 2)];
            float a[4] = {aq.x, aq.y, aq.z, aq.w};
            float bb2[4] = {bk.x, bk.y, bk.z, bk.w};
#pragma unroll
            for (int i = 0; i < 4; i++)
#pragma unroll
                for (int j = 0; j < 4; j++) s4[i][j] += a[i] * bb2[j];
        }

        float addm[4];
#pragma unroll
        for (int j = 0; j < 4; j++) addm[j] = sv[tx * 4 + j];

        float alpha[4];
#pragma unroll
        for (int i = 0; i < 4; i++) {
            float rmax = -INFINITY;
#pragma unroll
            for (int j = 0; j < 4; j++) {
                s4[i][j] = s4[i][j] * scale + addm[j];
                rmax = fmaxf(rmax, s4[i][j]);
            }
#pragma unroll
            for (int off = 8; off > 0; off >>= 1)
                rmax = fmaxf(rmax, __shfl_xor_sync(0xffffffffu, rmax, off));
            float mn = fmaxf(m_i[i], rmax);
            float ps = 0.f;
#pragma unroll
            for (int j = 0; j < 4; j++) {
                float p = __expf(s4[i][j] - mn);
                s4[i][j] = p;
                ps += p;
            }
#pragma unroll
            for (int off = 8; off > 0; off >>= 1)
                ps += __shfl_xor_sync(0xffffffffu, ps, off);
            float al = __expf(m_i[i] - mn);
            l_i[i] = l_i[i] * al + ps;
            m_i[i] = mn;
            alpha[i] = al;
#pragma unroll
            for (int j = 0; j < 4; j++)
                Ps[(ty * 4 + i) * 65 + tx * 4 + j] = s4[i][j];
        }
        __syncthreads();

#pragma unroll
        for (int i = 0; i < 4; i++)
#pragma unroll
            for (int j = 0; j < 8; j++) o[i][j] *= alpha[i];

#pragma unroll 2
        for (int kk = 0; kk < 64; kk++) {
            float4 v0 = *(const float4*)&Vs[(kk << 7) + (tx << 2)];
            float4 v1 = *(const float4*)&Vs[(kk << 7) + 64 + (tx << 2)];
#pragma unroll
            for (int i = 0; i < 4; i++) {
                float p = Ps[(ty * 4 + i) * 65 + kk];
                o[i][0] += p * v0.x; o[i][1] += p * v0.y;
                o[i][2] += p * v0.z; o[i][3] += p * v0.w;
                o[i][4] += p * v1.x; o[i][5] += p * v1.y;
                o[i][6] += p * v1.z; o[i][7] += p * v1.w;
            }
        }
    }

#pragma unroll
    for (int i = 0; i < 4; i++) {
        int row = qt * 64 + ty * 4 + i;
        float f = visb[row] ? (1.f / l_i[i]) : 0.f;
        float* op = outp + (tokbase + row) * DIMC + h * HD;
#pragma unroll
        for (int half = 0; half < 2; half++) {
            float4 w;
            w.x = __uint_as_float(f2tf32(o[i][half * 4 + 0] * f));
            w.y = __uint_as_float(f2tf32(o[i][half * 4 + 1] * f));
            w.z = __uint_as_float(f2tf32(o[i][half * 4 + 2] * f));
            w.w = __uint_as_float(f2tf32(o[i][half * 4 + 3] * f));
            *(float4*)(op + half * 64 + tx * 4) = w;
        }
    }
}

// ---------------------------------------------------------------------------
extern "C" void kernel_launch(void* const* d_in, const int* in_sizes, int n_in,
                              void* d_out, int out_size)
{
    const float* x    = (const float*)d_in[0];
    const float* wqkv = (const float*)d_in[1];
    const float* wo   = (const float*)d_in[2];
    const float* qw   = (const float*)d_in[3];
    const float* kw   = (const float*)d_in[4];
    const float* fc   = (const float*)d_in[5];
    const float* fs   = (const float*)d_in[6];
    const unsigned char* visraw = (const unsigned char*)d_in[7];
    float* out = (float*)d_out;

    float *qkv, *attn, *xr, *wqr, *wor;
    unsigned char* mask;
    cudaGetSymbolAddress((void**)&qkv, g_qkv);
    cudaGetSymbolAddress((void**)&attn, g_attn);
    cudaGetSymbolAddress((void**)&xr, g_xr);
    cudaGetSymbolAddress((void**)&wqr, g_wqr);
    cudaGetSymbolAddress((void**)&wor, g_wor);
    cudaGetSymbolAddress((void**)&mask, g_mask);

    // 0) Mask canonicalization + tf32 pre-rounding of GEMM operands
    mask_prep<<<1, 256>>>(visraw);
    round_tf32<<<1184, 256>>>((const float4*)x, (float4*)xr, BB * SS * DIMC / 4);
    round_tf32<<<1184, 256>>>((const float4*)wqkv, (float4*)wqr, QKVC * DIMC / 4);
    round_tf32<<<1184, 256>>>((const float4*)wo, (float4*)wor, DIMC * DIMC / 4);

    // 1) QKV projection (tf32 mma.sync): [8192,2048] x [3072,2048]^T
    cudaFuncSetAttribute(gemm_mma, cudaFuncAttributeMaxDynamicSharedMemorySize, GEMM_SMEM);
    gemm_mma<<<dim3(QKVC / 128, (BB * SS) / 128), 256, GEMM_SMEM>>>(
        xr, wqr, qkv, BB * SS, QKVC, DIMC);

    // 2) RMSNorm + RoPE on q & k heads (in place)
    norm_rope_kernel<<<dim3(NH + NKV, SS, BB), 128>>>(qkv, qw, kw, fc, fs);

    // 3) Attention (fp32 SIMT flash; output pre-rounded to tf32)
    cudaFuncSetAttribute(attn_kernel, cudaFuncAttributeMaxDynamicSharedMemorySize,
                         ATT_SMEM_BYTES);
    attn_kernel<<<dim3(SS / 64, NH, BB), 256, ATT_SMEM_BYTES>>>(qkv, mask, attn);

    // 4) Output projection (tf32 mma.sync): [8192,2048] x [2048,2048]^T
    gemm_mma<<<dim3(DIMC / 128, (BB * SS) / 128), 256, GEMM_SMEM>>>(
        attn, wor, out, BB * SS, DIMC, DIMC);
}

// round 9
// speedup vs baseline: 4.8466x; 2.5036x over previous
#include <cuda_runtime.h>
#include <math.h>
#include <cstdint>

#define BB   4
#define SS   2048
#define DIMC 2048
#define NH   16
#define NKV  4
#define HD   128
#define QKVC 3072
#define EPSF 1.1920928955078125e-07f
#define NEGF -1e30f

// Scratch (device globals: allocation-free per harness rules)
__device__ float g_qkv[(size_t)BB * SS * QKVC];   // 96 MB
__device__ float g_attn[(size_t)BB * SS * DIMC];  // 64 MB  (tf32-rounded by attn)
__device__ float g_xr[(size_t)BB * SS * DIMC];    // 64 MB  x rounded to tf32
__device__ float g_wqr[(size_t)QKVC * DIMC];      // 24 MB  wqkv rounded
__device__ float g_wor[(size_t)DIMC * DIMC];      // 16 MB  wo rounded
__device__ unsigned char g_mask[BB * SS];         // canonical 0/1 mask

// ===========================================================================
// Portable helpers (sm_80-baseline ISA only; NO 'a'-suffix features)
// ===========================================================================
__device__ __forceinline__ uint32_t smem_u32(const void* p) {
    uint32_t a;
    asm("{ .reg .u64 t; cvta.to.shared.u64 t, %1; cvt.u32.u64 %0, t; }" : "=r"(a) : "l"(p));
    return a;
}
__device__ __forceinline__ void cp16(uint32_t s, const void* g) {
    asm volatile("cp.async.cg.shared.global [%0], [%1], 16;" :: "r"(s), "l"(g));
}
#define CP_COMMIT() asm volatile("cp.async.commit_group;" ::: "memory")
#define CP_WAIT(n)  asm volatile("cp.async.wait_group %0;" :: "n"(n) : "memory")

__device__ __forceinline__ uint32_t f2tf32(float f) {
    uint32_t r;
    asm("cvt.rna.tf32.f32 %0, %1;" : "=r"(r) : "f"(f));
    return r;
}
__device__ __forceinline__ void mma_tf32(float* c, uint32_t a0, uint32_t a1,
                                         uint32_t a2, uint32_t a3,
                                         uint32_t b0, uint32_t b1) {
    asm volatile(
        "mma.sync.aligned.m16n8k8.row.col.f32.tf32.tf32.f32 "
        "{%0,%1,%2,%3}, {%4,%5,%6,%7}, {%8,%9}, {%0,%1,%2,%3};"
        : "+f"(c[0]), "+f"(c[1]), "+f"(c[2]), "+f"(c[3])
        : "r"(a0), "r"(a1), "r"(a2), "r"(a3), "r"(b0), "r"(b1));
}

// ===========================================================================
// Elementwise tf32 pre-round: out[i] = rna_tf32(in[i]) as f32 bits.
// ===========================================================================
__global__ __launch_bounds__(256) void round_tf32(const float4* __restrict__ in,
                                                  float4* __restrict__ out, int n4)
{
    for (int i = blockIdx.x * 256 + threadIdx.x; i < n4; i += gridDim.x * 256) {
        float4 v = in[i];
        v.x = __uint_as_float(f2tf32(v.x));
        v.y = __uint_as_float(f2tf32(v.y));
        v.z = __uint_as_float(f2tf32(v.z));
        v.w = __uint_as_float(f2tf32(v.w));
        out[i] = v;
    }
}

// ===========================================================================
// Mask canonicalization (dtype-robust): writes 0/1 bytes into g_mask.
// ===========================================================================
__global__ __launch_bounds__(256) void mask_prep(const unsigned char* __restrict__ raw)
{
    __shared__ int kind;  // 0=int32, 1=bool/u8, 2=float32
    if (threadIdx.x == 0) kind = 0;
    __syncthreads();
    const int NTOK = BB * SS;
    for (int i = threadIdx.x; i < NTOK; i += 256) {
        unsigned char v = raw[i];
        if ((i & 3) == 3 && v == 0x3F) kind = 2;
        else if ((i & 3) != 0 && v != 0) kind = 1;
    }
    __syncthreads();
    int k = kind;
    for (int i = threadIdx.x; i < NTOK; i += 256) {
        unsigned char m;
        if (k == 2)      m = (((const float*)raw)[i] != 0.0f);
        else if (k == 1) m = (raw[i] != 0);
        else             m = (((const int*)raw)[i] != 0);
        g_mask[i] = m;
    }
}

// ===========================================================================
// TF32 mma.sync GEMM (unchanged from R8-passing version).
// ===========================================================================
#define AROW    36
#define TILEF   (128 * AROW)
#define STAGEF  (2 * TILEF)
#define GSTAGES 3
#define GEMM_SMEM (GSTAGES * STAGEF * 4)   // 110592 B

__device__ __forceinline__ void ld_stage(uint32_t sA, uint32_t sB,
                                         const float* gA, const float* gB,
                                         int K, int kof, int t)
{
    const int q = t & 7;
    const int r0 = t >> 3;
#pragma unroll
    for (int i = 0; i < 4; i++) {
        const int r = r0 + 32 * i;
        const uint32_t soff = (uint32_t)(r * AROW + q * 4) * 4u;
        cp16(sA + soff, gA + (size_t)r * K + kof + q * 4);
        cp16(sB + soff, gB + (size_t)r * K + kof + q * 4);
    }
}

__global__ __launch_bounds__(256, 2) void gemm_mma(const float* __restrict__ A,
                                                   const float* __restrict__ Bm,
                                                   float* __restrict__ C,
                                                   int M, int N, int K)
{
    extern __shared__ __align__(16) float sm[];
    const int t = threadIdx.x;
    const int lane = t & 31;
    const int wid = t >> 5;
    const int wr = wid >> 2;
    const int wc = wid & 3;
    const int g = lane >> 2;
    const int q = lane & 3;
    const int m0 = blockIdx.y * 128;
    const int n0 = blockIdx.x * 128;
    const int NK = K >> 5;
    const uint32_t smb = smem_u32(sm);

    const float* gA = A + (size_t)m0 * K;
    const float* gB = Bm + (size_t)n0 * K;

    float c[4][4][4];
#pragma unroll
    for (int i = 0; i < 4; i++)
#pragma unroll
        for (int j = 0; j < 4; j++)
#pragma unroll
            for (int r = 0; r < 4; r++) c[i][j][r] = 0.f;

#pragma unroll
    for (int s = 0; s < 2; s++) {
        uint32_t sb = smb + s * STAGEF * 4;
        ld_stage(sb, sb + TILEF * 4, gA, gB, K, s * 32, t);
        CP_COMMIT();
    }

    for (int kt = 0; kt < NK; kt++) {
        CP_WAIT(1);
        __syncthreads();

        const uint32_t* As = (const uint32_t*)(sm + (kt % 3) * STAGEF);
        const uint32_t* Aw = As + (wr * 64) * AROW;
        const uint32_t* Bw = As + TILEF + (wc * 32) * AROW;

#pragma unroll
        for (int ks = 0; ks < 4; ks++) {
            const int k0 = ks * 8;
            uint32_t bf[4][2];
#pragma unroll
            for (int j = 0; j < 4; j++) {
                bf[j][0] = Bw[(j * 8 + g) * AROW + k0 + q];
                bf[j][1] = Bw[(j * 8 + g) * AROW + k0 + 4 + q];
            }
#pragma unroll
            for (int i = 0; i < 4; i++) {
                uint32_t a0 = Aw[(i * 16 + g) * AROW + k0 + q];
                uint32_t a1 = Aw[(i * 16 + 8 + g) * AROW + k0 + q];
                uint32_t a2 = Aw[(i * 16 + g) * AROW + k0 + 4 + q];
                uint32_t a3 = Aw[(i * 16 + 8 + g) * AROW + k0 + 4 + q];
#pragma unroll
                for (int j = 0; j < 4; j++)
                    mma_tf32(c[i][j], a0, a1, a2, a3, bf[j][0], bf[j][1]);
            }
        }

        const int pf = kt + 2;
        if (pf < NK) {
            uint32_t sb = smb + (pf % 3) * STAGEF * 4;
            ld_stage(sb, sb + TILEF * 4, gA, gB, K, pf * 32, t);
        }
        CP_COMMIT();
    }

#pragma unroll
    for (int i = 0; i < 4; i++) {
        const int row = m0 + wr * 64 + i * 16 + g;
#pragma unroll
        for (int j = 0; j < 4; j++) {
            const int col = n0 + wc * 32 + j * 8 + q * 2;
            *(float2*)(C + (size_t)row * N + col) = make_float2(c[i][j][0], c[i][j][1]);
            *(float2*)(C + (size_t)(row + 8) * N + col) = make_float2(c[i][j][2], c[i][j][3]);
        }
    }
}

// ===========================================================================
// Fused per-head RMSNorm + interleaved RoPE, tf32-rounded writes.
// heads 0..15: q (norm+rope). 16..19: k (norm+rope). 20..23: v (round only).
// ===========================================================================
__global__ __launch_bounds__(128) void norm_rope_kernel(float* __restrict__ qkv,
                                                        const float* __restrict__ qw,
                                                        const float* __restrict__ kw,
                                                        const float* __restrict__ fcos,
                                                        const float* __restrict__ fsin)
{
    const int head = blockIdx.x;   // 0..23
    const int s    = blockIdx.y;
    const int b    = blockIdx.z;
    const int t    = threadIdx.x;

    const size_t rowbase = ((size_t)(b * SS + s)) * QKVC;

    if (head >= NH + NKV) {  // V heads: tf32 round only
        const int off = DIMC + NKV * HD + (head - NH - NKV) * HD;
        float x = qkv[rowbase + off + t];
        qkv[rowbase + off + t] = __uint_as_float(f2tf32(x));
        return;
    }

    const int off = (head < NH) ? head * HD : DIMC + (head - NH) * HD;
    const float* w = (head < NH) ? qw : kw;

    float x = qkv[rowbase + off + t];

    float ssum = x * x;
#pragma unroll
    for (int o = 16; o > 0; o >>= 1) ssum += __shfl_xor_sync(0xffffffffu, ssum, o);
    __shared__ float red[4];
    if ((t & 31) == 0) red[t >> 5] = ssum;
    __syncthreads();
    float tot = red[0] + red[1] + red[2] + red[3];
    float r = rsqrtf(tot * (1.f / HD) + EPSF);

    float xn = x * r * w[t];
    float partner = __shfl_xor_sync(0xffffffffu, xn, 1);
    float rot = (t & 1) ? partner : -partner;
    float c = fcos[s * HD + t];
    float sn = fsin[s * HD + t];
    qkv[rowbase + off + t] = __uint_as_float(f2tf32(xn * c + rot * sn));
}

// ===========================================================================
// Flash attention via tf32 mma.sync.
// CTA: 128 rows = 2 q-heads x 64 queries, sharing one kv head.
// 8 warps, warp tile 16 rows x 64 keys (softmax fully warp-local).
// K/V double-buffered cp.async; Q frags register-resident; P via smem.
// ===========================================================================
#define ATKS 132                         // K row stride (floats)
#define ATVS 136                         // V row stride
#define ATPS 68                          // P row stride
#define KFL  (64 * ATKS)                 // 8448 floats
#define VFL  (64 * ATVS)                 // 8704
#define STFL (KFL + VFL)                 // 17152 floats per stage
#define POFL (2 * STFL)                  // 34304
#define SVFL (POFL + 128 * ATPS)         // 43008
#define ATT2_SMEM ((SVFL + 128 + 32) * 4)  // ~172KB

__device__ __forceinline__ void ld_kv(uint32_t sb, const float* Kg, const float* Vg, int t)
{
#pragma unroll
    for (int i = 0; i < 8; i++) {
        int id = t + 256 * i;
        int r = id >> 5, c = id & 31;
        cp16(sb + (uint32_t)(r * ATKS + c * 4) * 4u, Kg + (size_t)r * QKVC + c * 4);
    }
    uint32_t vb = sb + KFL * 4;
#pragma unroll
    for (int i = 0; i < 8; i++) {
        int id = t + 256 * i;
        int r = id >> 5, c = id & 31;
        cp16(vb + (uint32_t)(r * ATVS + c * 4) * 4u, Vg + (size_t)r * QKVC + c * 4);
    }
}

__global__ __launch_bounds__(256, 1) void attn_mma(const float* __restrict__ qkv,
                                                   const unsigned char* __restrict__ vis,
                                                   float* __restrict__ outp)
{
    extern __shared__ __align__(16) float smf[];
    const uint32_t smb = smem_u32(smf);
    const int t = threadIdx.x;
    const int lane = t & 31;
    const int w = t >> 5;
    const int g = lane >> 2;
    const int q = lane & 3;
    const int qt = blockIdx.x;
    const int hp = blockIdx.y;           // head pair 0..7
    const int b  = blockIdx.z;
    const int h  = hp * 2 + (w >> 2);    // this warp's q head
    const int kvh = hp >> 1;
    const int qrow = (w & 3) << 4;       // 0,16,32,48 within the 64-query tile

    const size_t tokbase = (size_t)b * SS;
    const unsigned char* visb = vis + tokbase;

    // ---- Q fragments to registers (reused across all key tiles) ----
    const float* Qb = qkv + (tokbase + qt * 64) * QKVC + h * HD;
    const float* Qg0 = Qb + (size_t)(qrow + g) * QKVC;
    const float* Qg1 = Qb + (size_t)(qrow + g + 8) * QKVC;
    uint32_t qf[16][4];
#pragma unroll
    for (int kc = 0; kc < 16; kc++) {
        qf[kc][0] = __float_as_uint(Qg0[kc * 8 + q]);
        qf[kc][1] = __float_as_uint(Qg1[kc * 8 + q]);
        qf[kc][2] = __float_as_uint(Qg0[kc * 8 + q + 4]);
        qf[kc][3] = __float_as_uint(Qg1[kc * 8 + q + 4]);
    }

    float* pwarp = smf + POFL + (16 * w) * ATPS;   // this warp's private P rows
    float* svb = smf + SVFL;                        // sv[2][64]

    float o[16][4];
#pragma unroll
    for (int nf = 0; nf < 16; nf++)
#pragma unroll
        for (int r = 0; r < 4; r++) o[nf][r] = 0.f;
    float m0p = -INFINITY, m1p = -INFINITY, l0 = 0.f, l1 = 0.f;
    const float scale = 0.08838834764831843f;   // 1/sqrt(128)

    const float* KB = qkv + tokbase * QKVC + DIMC + kvh * HD;

    // Prologue: stages 0,1
#pragma unroll
    for (int s = 0; s < 2; s++) {
        const float* Kg = KB + (size_t)(s * 64) * QKVC;
        ld_kv(smb + s * STFL * 4, Kg, Kg + NKV * HD, t);
        if (t < 64) svb[s * 64 + t] = visb[s * 64 + t] ? 0.f : NEGF;
        CP_COMMIT();
    }

    for (int kt = 0; kt < SS / 64; kt++) {
        CP_WAIT(1);
        __syncthreads();

        const float* ks = smf + (kt & 1) * STFL;
        const float* vs = ks + KFL;
        const float* svp = svb + (kt & 1) * 64;

        // ---- S = Q K^T  (8 n-frags of 8 keys each) ----
        float c8[8][4];
#pragma unroll
        for (int f = 0; f < 8; f++)
#pragma unroll
            for (int r = 0; r < 4; r++) c8[f][r] = 0.f;

#pragma unroll
        for (int kc = 0; kc < 16; kc++) {
            const float* kr = ks + kc * 8 + q;
#pragma unroll
            for (int f = 0; f < 8; f++) {
                uint32_t b0 = __float_as_uint(kr[(f * 8 + g) * ATKS]);
                uint32_t b1 = __float_as_uint(kr[(f * 8 + g) * ATKS + 4]);
                mma_tf32(c8[f], qf[kc][0], qf[kc][1], qf[kc][2], qf[kc][3], b0, b1);
            }
        }

        // ---- online softmax (warp-local: quad shuffles) ----
        float rmx0 = -INFINITY, rmx1 = -INFINITY;
#pragma unroll
        for (int f = 0; f < 8; f++) {
            float a0 = svp[8 * f + 2 * q], a1 = svp[8 * f + 2 * q + 1];
            c8[f][0] = c8[f][0] * scale + a0;
            c8[f][1] = c8[f][1] * scale + a1;
            c8[f][2] = c8[f][2] * scale + a0;
            c8[f][3] = c8[f][3] * scale + a1;
            rmx0 = fmaxf(rmx0, fmaxf(c8[f][0], c8[f][1]));
            rmx1 = fmaxf(rmx1, fmaxf(c8[f][2], c8[f][3]));
        }
        rmx0 = fmaxf(rmx0, __shfl_xor_sync(0xffffffffu, rmx0, 1));
        rmx0 = fmaxf(rmx0, __shfl_xor_sync(0xffffffffu, rmx0, 2));
        rmx1 = fmaxf(rmx1, __shfl_xor_sync(0xffffffffu, rmx1, 1));
        rmx1 = fmaxf(rmx1, __shfl_xor_sync(0xffffffffu, rmx1, 2));

        float mn0 = fmaxf(m0p, rmx0), mn1 = fmaxf(m1p, rmx1);
        float al0 = __expf(m0p - mn0), al1 = __expf(m1p - mn1);
        m0p = mn0; m1p = mn1;

        float ps0 = 0.f, ps1 = 0.f;
#pragma unroll
        for (int f = 0; f < 8; f++) {
            float p0 = __expf(c8[f][0] - mn0);
            float p1 = __expf(c8[f][1] - mn0);
            float p2 = __expf(c8[f][2] - mn1);
            float p3 = __expf(c8[f][3] - mn1);
            ps0 += p0 + p1; ps1 += p2 + p3;
            *(float2*)(pwarp + g * ATPS + 8 * f + 2 * q) =
                make_float2(__uint_as_float(f2tf32(p0)), __uint_as_float(f2tf32(p1)));
            *(float2*)(pwarp + (g + 8) * ATPS + 8 * f + 2 * q) =
                make_float2(__uint_as_float(f2tf32(p2)), __uint_as_float(f2tf32(p3)));
        }
        ps0 += __shfl_xor_sync(0xffffffffu, ps0, 1);
        ps0 += __shfl_xor_sync(0xffffffffu, ps0, 2);
        ps1 += __shfl_xor_sync(0xffffffffu, ps1, 1);
        ps1 += __shfl_xor_sync(0xffffffffu, ps1, 2);
        l0 = l0 * al0 + ps0;
        l1 = l1 * al1 + ps1;

        // rescale O
#pragma unroll
        for (int nf = 0; nf < 16; nf++) {
            o[nf][0] *= al0; o[nf][1] *= al0;
            o[nf][2] *= al1; o[nf][3] *= al1;
        }
        __syncwarp();

        // ---- O += P V ----
#pragma unroll
        for (int kc = 0; kc < 8; kc++) {
            uint32_t a0 = __float_as_uint(pwarp[g * ATPS + kc * 8 + q]);
            uint32_t a1 = __float_as_uint(pwarp[(g + 8) * ATPS + kc * 8 + q]);
            uint32_t a2 = __float_as_uint(pwarp[g * ATPS + kc * 8 + q + 4]);
            uint32_t a3 = __float_as_uint(pwarp[(g + 8) * ATPS + kc * 8 + q + 4]);
            const float* vr0 = vs + (kc * 8 + q) * ATVS + g;
            const float* vr1 = vs + (kc * 8 + q + 4) * ATVS + g;
#pragma unroll
            for (int nf = 0; nf < 16; nf++) {
                uint32_t b0 = __float_as_uint(vr0[nf * 8]);
                uint32_t b1 = __float_as_uint(vr1[nf * 8]);
                mma_tf32(o[nf], a0, a1, a2, a3, b0, b1);
            }
        }

        __syncthreads();
        const int pf = kt + 2;
        if (pf < SS / 64) {
            const float* Kg = KB + (size_t)(pf * 64) * QKVC;
            ld_kv(smb + (pf & 1) * STFL * 4, Kg, Kg + NKV * HD, t);
            if (t < 64) svb[(pf & 1) * 64 + t] = visb[pf * 64 + t] ? 0.f : NEGF;
        }
        CP_COMMIT();
    }

    // ---- epilogue: normalize, zero invisible q rows, tf32-round ----
    const int r0 = qt * 64 + qrow + g;
    const int r1 = r0 + 8;
    const float f0 = visb[r0] ? (1.f / l0) : 0.f;
    const float f1 = visb[r1] ? (1.f / l1) : 0.f;
    float* o0 = outp + (tokbase + r0) * DIMC + h * HD;
    float* o1 = outp + (tokbase + r1) * DIMC + h * HD;
#pragma unroll
    for (int nf = 0; nf < 16; nf++) {
        *(float2*)(o0 + nf * 8 + 2 * q) =
            make_float2(__uint_as_float(f2tf32(o[nf][0] * f0)),
                        __uint_as_float(f2tf32(o[nf][1] * f0)));
        *(float2*)(o1 + nf * 8 + 2 * q) =
            make_float2(__uint_as_float(f2tf32(o[nf][2] * f1)),
                        __uint_as_float(f2tf32(o[nf][3] * f1)));
    }
}

// ---------------------------------------------------------------------------
extern "C" void kernel_launch(void* const* d_in, const int* in_sizes, int n_in,
                              void* d_out, int out_size)
{
    const float* x    = (const float*)d_in[0];
    const float* wqkv = (const float*)d_in[1];
    const float* wo   = (const float*)d_in[2];
    const float* qw   = (const float*)d_in[3];
    const float* kw   = (const float*)d_in[4];
    const float* fc   = (const float*)d_in[5];
    const float* fs   = (const float*)d_in[6];
    const unsigned char* visraw = (const unsigned char*)d_in[7];
    float* out = (float*)d_out;

    float *qkv, *attn, *xr, *wqr, *wor;
    unsigned char* mask;
    cudaGetSymbolAddress((void**)&qkv, g_qkv);
    cudaGetSymbolAddress((void**)&attn, g_attn);
    cudaGetSymbolAddress((void**)&xr, g_xr);
    cudaGetSymbolAddress((void**)&wqr, g_wqr);
    cudaGetSymbolAddress((void**)&wor, g_wor);
    cudaGetSymbolAddress((void**)&mask, g_mask);

    // 0) Mask canonicalization + tf32 pre-rounding of GEMM operands
    mask_prep<<<1, 256>>>(visraw);
    round_tf32<<<1184, 256>>>((const float4*)x, (float4*)xr, BB * SS * DIMC / 4);
    round_tf32<<<1184, 256>>>((const float4*)wqkv, (float4*)wqr, QKVC * DIMC / 4);
    round_tf32<<<1184, 256>>>((const float4*)wo, (float4*)wor, DIMC * DIMC / 4);

    // 1) QKV projection (tf32 mma.sync): [8192,2048] x [3072,2048]^T
    cudaFuncSetAttribute(gemm_mma, cudaFuncAttributeMaxDynamicSharedMemorySize, GEMM_SMEM);
    gemm_mma<<<dim3(QKVC / 128, (BB * SS) / 128), 256, GEMM_SMEM>>>(
        xr, wqr, qkv, BB * SS, QKVC, DIMC);

    // 2) RMSNorm + RoPE (q,k) + tf32 rounding (q,k,v)
    norm_rope_kernel<<<dim3(NH + 2 * NKV, SS, BB), 128>>>(qkv, qw, kw, fc, fs);

    // 3) Attention (tf32 mma.sync flash)
    cudaFuncSetAttribute(attn_mma, cudaFuncAttributeMaxDynamicSharedMemorySize, ATT2_SMEM);
    attn_mma<<<dim3(SS / 64, NH / 2, BB), 256, ATT2_SMEM>>>(qkv, mask, attn);

    // 4) Output projection (tf32 mma.sync): [8192,2048] x [2048,2048]^T
    gemm_mma<<<dim3(DIMC / 128, (BB * SS) / 128), 256, GEMM_SMEM>>>(
        attn, wor, out, BB * SS, DIMC, DIMC);
}

// round 10
// speedup vs baseline: 7.9006x; 1.6301x over previous
#include <cuda_runtime.h>
#include <cuda_fp16.h>
#include <math.h>
#include <cstdint>

#define BB   4
#define SS   2048
#define DIMC 2048
#define NH   16
#define NKV  4
#define HD   128
#define QKVC 3072
#define EPSF 1.1920928955078125e-07f
#define NEGF -1e30f

// Scratch (device globals: allocation-free per harness rules)
__device__ float  g_qkv[(size_t)BB * SS * QKVC];    // 96 MB fp32 (gemm1 out)
__device__ __half g_qkvh[(size_t)BB * SS * QKVC];   // 48 MB fp16 (norm/rope out)
__device__ __half g_attnh[(size_t)BB * SS * DIMC];  // 32 MB fp16 (attn out)
__device__ __half g_xh[(size_t)BB * SS * DIMC];     // 32 MB
__device__ __half g_wqh[(size_t)QKVC * DIMC];       // 12 MB
__device__ __half g_woh[(size_t)DIMC * DIMC];       //  8 MB
__device__ unsigned char g_mask[BB * SS];

// ===========================================================================
// Portable helpers (sm_80-baseline ISA; no 'a'-suffix features)
// ===========================================================================
__device__ __forceinline__ uint32_t smem_u32(const void* p) {
    uint32_t a;
    asm("{ .reg .u64 t; cvta.to.shared.u64 t, %1; cvt.u32.u64 %0, t; }" : "=r"(a) : "l"(p));
    return a;
}
__device__ __forceinline__ void cp16(uint32_t s, const void* g) {
    asm volatile("cp.async.cg.shared.global [%0], [%1], 16;" :: "r"(s), "l"(g));
}
#define CP_COMMIT() asm volatile("cp.async.commit_group;" ::: "memory")
#define CP_WAIT(n)  asm volatile("cp.async.wait_group %0;" :: "n"(n) : "memory")

__device__ __forceinline__ void ldsm4(uint32_t* r, uint32_t a) {
    asm volatile("ldmatrix.sync.aligned.m8n8.x4.shared.b16 {%0,%1,%2,%3}, [%4];"
                 : "=r"(r[0]), "=r"(r[1]), "=r"(r[2]), "=r"(r[3]) : "r"(a));
}
__device__ __forceinline__ void ldsm4t(uint32_t* r, uint32_t a) {
    asm volatile("ldmatrix.sync.aligned.m8n8.x4.trans.shared.b16 {%0,%1,%2,%3}, [%4];"
                 : "=r"(r[0]), "=r"(r[1]), "=r"(r[2]), "=r"(r[3]) : "r"(a));
}
__device__ __forceinline__ void mma_f16(float* c, uint32_t a0, uint32_t a1,
                                        uint32_t a2, uint32_t a3,
                                        uint32_t b0, uint32_t b1) {
    asm volatile(
        "mma.sync.aligned.m16n8k16.row.col.f32.f16.f16.f32 "
        "{%0,%1,%2,%3}, {%4,%5,%6,%7}, {%8,%9}, {%0,%1,%2,%3};"
        : "+f"(c[0]), "+f"(c[1]), "+f"(c[2]), "+f"(c[3])
        : "r"(a0), "r"(a1), "r"(a2), "r"(a3), "r"(b0), "r"(b1));
}

// ===========================================================================
// fp32 -> fp16 conversion (elementwise)
// ===========================================================================
__global__ __launch_bounds__(256) void cvt_half(const float2* __restrict__ in,
                                                __half2* __restrict__ out, int n2)
{
    for (int i = blockIdx.x * 256 + threadIdx.x; i < n2; i += gridDim.x * 256) {
        float2 v = in[i];
        out[i] = __floats2half2_rn(v.x, v.y);
    }
}

// ===========================================================================
// Mask canonicalization (dtype-robust): writes 0/1 bytes into g_mask.
// ===========================================================================
__global__ __launch_bounds__(256) void mask_prep(const unsigned char* __restrict__ raw)
{
    __shared__ int kind;  // 0=int32, 1=bool/u8, 2=float32
    if (threadIdx.x == 0) kind = 0;
    __syncthreads();
    const int NTOK = BB * SS;
    for (int i = threadIdx.x; i < NTOK; i += 256) {
        unsigned char v = raw[i];
        if ((i & 3) == 3 && v == 0x3F) kind = 2;
        else if ((i & 3) != 0 && v != 0) kind = 1;
    }
    __syncthreads();
    int k = kind;
    for (int i = threadIdx.x; i < NTOK; i += 256) {
        unsigned char m;
        if (k == 2)      m = (((const float*)raw)[i] != 0.0f);
        else if (k == 1) m = (raw[i] != 0);
        else             m = (((const int*)raw)[i] != 0);
        g_mask[i] = m;
    }
}

// ===========================================================================
// FP16 mma.sync GEMM: C[M,N](f32) = A[M,K] * B[N,K]^T, A/B fp16.
// CTA 128x128, K-tile 64 halfs, 3-stage cp.async, 8 warps (2x4), warp 64x32.
// ldmatrix.x4 fragment loads. 2 CTAs/SM.
// ===========================================================================
#define HROW   72                        // halfs per smem row (64 + 8 pad)
#define HTILE  (128 * HROW)              // halfs per operand tile
#define HSTAGE (2 * HTILE)
#define HGEMM_SMEM (3 * HSTAGE * 2)      // 110592 B

__device__ __forceinline__ void ld_stage_h(uint32_t sb, const __half* gA,
                                           const __half* gB, int K, int kof, int t)
{
    const int cq = t & 7;
    const int r0 = t >> 3;
#pragma unroll
    for (int i = 0; i < 4; i++) {
        const int r = r0 + 32 * i;
        const uint32_t so = (uint32_t)(r * HROW + cq * 8) * 2u;
        cp16(sb + so, gA + (size_t)r * K + kof + cq * 8);
        cp16(sb + HTILE * 2 + so, gB + (size_t)r * K + kof + cq * 8);
    }
}

__global__ __launch_bounds__(256, 2) void gemm_h(const __half* __restrict__ A,
                                                 const __half* __restrict__ Bm,
                                                 float* __restrict__ C,
                                                 int M, int N, int K)
{
    extern __shared__ __align__(16) char smc[];
    const uint32_t smb = smem_u32(smc);
    const int t = threadIdx.x;
    const int lane = t & 31;
    const int wid = t >> 5;
    const int wr = wid >> 2;
    const int wc = wid & 3;
    const int g = lane >> 2;
    const int q = lane & 3;
    const int m0 = blockIdx.y * 128;
    const int n0 = blockIdx.x * 128;
    const int NK = K >> 6;

    const __half* gA = A + (size_t)m0 * K;
    const __half* gB = Bm + (size_t)n0 * K;

    float c[4][4][4];
#pragma unroll
    for (int i = 0; i < 4; i++)
#pragma unroll
        for (int j = 0; j < 4; j++)
#pragma unroll
            for (int r = 0; r < 4; r++) c[i][j][r] = 0.f;

#pragma unroll
    for (int s = 0; s < 2; s++) {
        ld_stage_h(smb + s * HSTAGE * 2, gA, gB, K, s * 64, t);
        CP_COMMIT();
    }

    // ldmatrix lane address components: row = (lane&15), +8 halfs if lane>=16
    const uint32_t lrow = (uint32_t)(lane & 15);
    const uint32_t lhi  = (uint32_t)(lane >> 4) * 8u;

    for (int kt = 0; kt < NK; kt++) {
        CP_WAIT(1);
        __syncthreads();

        const uint32_t st = smb + (kt % 3) * HSTAGE * 2;
        const uint32_t aB = st + ((wr * 64 + lrow) * HROW + lhi) * 2;
        const uint32_t bB = st + HTILE * 2 + ((wc * 32 + lrow) * HROW + lhi) * 2;

#pragma unroll
        for (int ks = 0; ks < 4; ks++) {
            uint32_t bf[4][2];
#pragma unroll
            for (int j = 0; j < 2; j++) {
                uint32_t r[4];
                ldsm4(r, bB + (uint32_t)(j * 16 * HROW * 2 + ks * 32));
                bf[2 * j][0] = r[0]; bf[2 * j + 1][0] = r[1];
                bf[2 * j][1] = r[2]; bf[2 * j + 1][1] = r[3];
            }
#pragma unroll
            for (int i = 0; i < 4; i++) {
                uint32_t a[4];
                ldsm4(a, aB + (uint32_t)(i * 16 * HROW * 2 + ks * 32));
#pragma unroll
                for (int j = 0; j < 4; j++)
                    mma_f16(c[i][j], a[0], a[1], a[2], a[3], bf[j][0], bf[j][1]);
            }
        }

        const int pf = kt + 2;
        if (pf < NK)
            ld_stage_h(smb + (pf % 3) * HSTAGE * 2, gA, gB, K, pf * 64, t);
        CP_COMMIT();
    }

#pragma unroll
    for (int i = 0; i < 4; i++) {
        const int row = m0 + wr * 64 + i * 16 + g;
#pragma unroll
        for (int j = 0; j < 4; j++) {
            const int col = n0 + wc * 32 + j * 8 + q * 2;
            *(float2*)(C + (size_t)row * N + col) = make_float2(c[i][j][0], c[i][j][1]);
            *(float2*)(C + (size_t)(row + 8) * N + col) = make_float2(c[i][j][2], c[i][j][3]);
        }
    }
}

// ===========================================================================
// Fused per-head RMSNorm + interleaved RoPE; fp32 in, fp16 out.
// heads 0..15: q. 16..19: k. 20..23: v (convert only).
// ===========================================================================
__global__ __launch_bounds__(128) void norm_rope_h(const float* __restrict__ qkv,
                                                   __half* __restrict__ qkvh,
                                                   const float* __restrict__ qw,
                                                   const float* __restrict__ kw,
                                                   const float* __restrict__ fcos,
                                                   const float* __restrict__ fsin)
{
    const int head = blockIdx.x;
    const int s    = blockIdx.y;
    const int b    = blockIdx.z;
    const int t    = threadIdx.x;

    const size_t rowbase = ((size_t)(b * SS + s)) * QKVC;

    if (head >= NH + NKV) {  // V heads: convert only
        const int off = DIMC + NKV * HD + (head - NH - NKV) * HD;
        qkvh[rowbase + off + t] = __float2half_rn(qkv[rowbase + off + t]);
        return;
    }

    const int off = (head < NH) ? head * HD : DIMC + (head - NH) * HD;
    const float* w = (head < NH) ? qw : kw;

    float x = qkv[rowbase + off + t];

    float ssum = x * x;
#pragma unroll
    for (int o = 16; o > 0; o >>= 1) ssum += __shfl_xor_sync(0xffffffffu, ssum, o);
    __shared__ float red[4];
    if ((t & 31) == 0) red[t >> 5] = ssum;
    __syncthreads();
    float tot = red[0] + red[1] + red[2] + red[3];
    float r = rsqrtf(tot * (1.f / HD) + EPSF);

    float xn = x * r * w[t];
    float partner = __shfl_xor_sync(0xffffffffu, xn, 1);
    float rot = (t & 1) ? partner : -partner;
    float cc = fcos[s * HD + t];
    float sn = fsin[s * HD + t];
    qkvh[rowbase + off + t] = __float2half_rn(xn * cc + rot * sn);
}

// ===========================================================================
// FP16 flash attention. CTA: 128 rows = 2 q-heads x 64 queries, shared kv head.
// 8 warps, warp 16 rows x 64 keys. K/V double-buffered cp.async, ldmatrix
// frags (trans for V), softmax fp32 warp-local, P via fp16 smem.
// ===========================================================================
#define AKROW 136                          // K/V smem row: 128 + 8 halfs
#define KTH   (64 * AKROW)                 // halfs per K (or V) tile
#define STH   (2 * KTH)                    // halfs per stage
#define POH   (2 * STH)                    // P offset (halfs)
#define PROW  72
#define SVB   ((POH + 128 * PROW) * 2)     // sv byte offset
#define ATTH_SMEM (SVB + 2 * 64 * 4 + 64)  // ~89KB

__device__ __forceinline__ void ld_kv_h(uint32_t sb, const __half* Kg,
                                        const __half* Vg, int t)
{
    const int c = t & 15;
    const int r0 = t >> 4;
#pragma unroll
    for (int i = 0; i < 4; i++) {
        const int r = r0 + 16 * i;
        const uint32_t so = (uint32_t)(r * AKROW + c * 8) * 2u;
        cp16(sb + so, Kg + (size_t)r * QKVC + c * 8);
        cp16(sb + KTH * 2 + so, Vg + (size_t)r * QKVC + c * 8);
    }
}

__global__ __launch_bounds__(256, 1) void attn_h(const __half* __restrict__ qkvh,
                                                 const unsigned char* __restrict__ vis,
                                                 __half* __restrict__ outp)
{
    extern __shared__ __align__(16) char smc[];
    __half* hsm = (__half*)smc;
    const uint32_t smb = smem_u32(smc);
    const int t = threadIdx.x;
    const int lane = t & 31;
    const int w = t >> 5;
    const int g = lane >> 2;
    const int q = lane & 3;
    const int qt = blockIdx.x;
    const int hp = blockIdx.y;
    const int b  = blockIdx.z;
    const int h  = hp * 2 + (w >> 2);
    const int kvh = hp >> 1;
    const int qrow = (w & 3) << 4;

    const size_t tokbase = (size_t)b * SS;
    const unsigned char* visb = vis + tokbase;

    // Q fragments from gmem (fp16, b32 loads)
    const __half* Qb = qkvh + (tokbase + qt * 64) * QKVC + h * HD;
    const __half* Qg0 = Qb + (size_t)(qrow + g) * QKVC;
    const __half* Qg1 = Qb + (size_t)(qrow + g + 8) * QKVC;
    uint32_t qf[8][4];
#pragma unroll
    for (int kc = 0; kc < 8; kc++) {
        qf[kc][0] = *(const uint32_t*)(Qg0 + kc * 16 + 2 * q);
        qf[kc][1] = *(const uint32_t*)(Qg1 + kc * 16 + 2 * q);
        qf[kc][2] = *(const uint32_t*)(Qg0 + kc * 16 + 8 + 2 * q);
        qf[kc][3] = *(const uint32_t*)(Qg1 + kc * 16 + 8 + 2 * q);
    }

    __half* pwarp = hsm + POH + (16 * w) * PROW;
    float* svb = (float*)(smc + SVB);

    float o[16][4];
#pragma unroll
    for (int nf = 0; nf < 16; nf++)
#pragma unroll
        for (int r = 0; r < 4; r++) o[nf][r] = 0.f;
    float m0p = -INFINITY, m1p = -INFINITY, l0 = 0.f, l1 = 0.f;
    const float scale = 0.08838834764831843f;

    const __half* KB = qkvh + tokbase * QKVC + DIMC + kvh * HD;

#pragma unroll
    for (int s = 0; s < 2; s++) {
        const __half* Kg = KB + (size_t)(s * 64) * QKVC;
        ld_kv_h(smb + s * STH * 2, Kg, Kg + NKV * HD, t);
        if (t < 64) svb[s * 64 + t] = visb[s * 64 + t] ? 0.f : NEGF;
        CP_COMMIT();
    }

    const uint32_t lrow = (uint32_t)(lane & 15);
    const uint32_t lhi  = (uint32_t)(lane >> 4) * 8u;

    for (int kt = 0; kt < SS / 64; kt++) {
        CP_WAIT(1);
        __syncthreads();

        const uint32_t ksb = smb + (kt & 1) * STH * 2;
        const uint32_t vsb = ksb + KTH * 2;
        const float* svp = svb + (kt & 1) * 64;

        // ---- S = Q K^T ----
        float c8[8][4];
#pragma unroll
        for (int f = 0; f < 8; f++)
#pragma unroll
            for (int r = 0; r < 4; r++) c8[f][r] = 0.f;

        const uint32_t kfB = ksb + (lrow * AKROW + lhi) * 2;
#pragma unroll
        for (int kc = 0; kc < 8; kc++) {
#pragma unroll
            for (int fb = 0; fb < 4; fb++) {
                uint32_t r[4];
                ldsm4(r, kfB + (uint32_t)(fb * 16 * AKROW * 2 + kc * 32));
                mma_f16(c8[2 * fb],     qf[kc][0], qf[kc][1], qf[kc][2], qf[kc][3], r[0], r[2]);
                mma_f16(c8[2 * fb + 1], qf[kc][0], qf[kc][1], qf[kc][2], qf[kc][3], r[1], r[3]);
            }
        }

        // ---- online softmax (warp-local) ----
        float rmx0 = -INFINITY, rmx1 = -INFINITY;
#pragma unroll
        for (int f = 0; f < 8; f++) {
            float a0 = svp[8 * f + 2 * q], a1 = svp[8 * f + 2 * q + 1];
            c8[f][0] = c8[f][0] * scale + a0;
            c8[f][1] = c8[f][1] * scale + a1;
            c8[f][2] = c8[f][2] * scale + a0;
            c8[f][3] = c8[f][3] * scale + a1;
            rmx0 = fmaxf(rmx0, fmaxf(c8[f][0], c8[f][1]));
            rmx1 = fmaxf(rmx1, fmaxf(c8[f][2], c8[f][3]));
        }
        rmx0 = fmaxf(rmx0, __shfl_xor_sync(0xffffffffu, rmx0, 1));
        rmx0 = fmaxf(rmx0, __shfl_xor_sync(0xffffffffu, rmx0, 2));
        rmx1 = fmaxf(rmx1, __shfl_xor_sync(0xffffffffu, rmx1, 1));
        rmx1 = fmaxf(rmx1, __shfl_xor_sync(0xffffffffu, rmx1, 2));

        float mn0 = fmaxf(m0p, rmx0), mn1 = fmaxf(m1p, rmx1);
        float al0 = __expf(m0p - mn0), al1 = __expf(m1p - mn1);
        m0p = mn0; m1p = mn1;

        float ps0 = 0.f, ps1 = 0.f;
#pragma unroll
        for (int f = 0; f < 8; f++) {
            float p0 = __expf(c8[f][0] - mn0);
            float p1 = __expf(c8[f][1] - mn0);
            float p2 = __expf(c8[f][2] - mn1);
            float p3 = __expf(c8[f][3] - mn1);
            ps0 += p0 + p1; ps1 += p2 + p3;
            *(__half2*)(pwarp + g * PROW + f * 8 + 2 * q) = __floats2half2_rn(p0, p1);
            *(__half2*)(pwarp + (g + 8) * PROW + f * 8 + 2 * q) = __floats2half2_rn(p2, p3);
        }
        ps0 += __shfl_xor_sync(0xffffffffu, ps0, 1);
        ps0 += __shfl_xor_sync(0xffffffffu, ps0, 2);
        ps1 += __shfl_xor_sync(0xffffffffu, ps1, 1);
        ps1 += __shfl_xor_sync(0xffffffffu, ps1, 2);
        l0 = l0 * al0 + ps0;
        l1 = l1 * al1 + ps1;

#pragma unroll
        for (int nf = 0; nf < 16; nf++) {
            o[nf][0] *= al0; o[nf][1] *= al0;
            o[nf][2] *= al1; o[nf][3] *= al1;
        }
        __syncwarp();

        // ---- O += P V ----
        const uint32_t vfB = vsb + (lrow * AKROW + lhi) * 2;
#pragma unroll
        for (int kc = 0; kc < 4; kc++) {
            uint32_t a0 = *(const uint32_t*)(pwarp + g * PROW + kc * 16 + 2 * q);
            uint32_t a1 = *(const uint32_t*)(pwarp + (g + 8) * PROW + kc * 16 + 2 * q);
            uint32_t a2 = *(const uint32_t*)(pwarp + g * PROW + kc * 16 + 8 + 2 * q);
            uint32_t a3 = *(const uint32_t*)(pwarp + (g + 8) * PROW + kc * 16 + 8 + 2 * q);
#pragma unroll
            for (int db = 0; db < 8; db++) {
                uint32_t r[4];
                ldsm4t(r, vfB + (uint32_t)(kc * 16 * AKROW * 2 + db * 32));
                mma_f16(o[2 * db],     a0, a1, a2, a3, r[0], r[1]);
                mma_f16(o[2 * db + 1], a0, a1, a2, a3, r[2], r[3]);
            }
        }

        __syncthreads();
        const int pf = kt + 2;
        if (pf < SS / 64) {
            const __half* Kg = KB + (size_t)(pf * 64) * QKVC;
            ld_kv_h(smb + (pf & 1) * STH * 2, Kg, Kg + NKV * HD, t);
            if (t < 64) svb[(pf & 1) * 64 + t] = visb[pf * 64 + t] ? 0.f : NEGF;
        }
        CP_COMMIT();
    }

    // ---- epilogue: normalize, zero invisible rows, fp16 out ----
    const int r0 = qt * 64 + qrow + g;
    const int r1 = r0 + 8;
    const float f0 = visb[r0] ? (1.f / l0) : 0.f;
    const float f1 = visb[r1] ? (1.f / l1) : 0.f;
    __half* o0 = outp + (tokbase + r0) * DIMC + h * HD;
    __half* o1 = outp + (tokbase + r1) * DIMC + h * HD;
#pragma unroll
    for (int nf = 0; nf < 16; nf++) {
        *(__half2*)(o0 + nf * 8 + 2 * q) = __floats2half2_rn(o[nf][0] * f0, o[nf][1] * f0);
        *(__half2*)(o1 + nf * 8 + 2 * q) = __floats2half2_rn(o[nf][2] * f1, o[nf][3] * f1);
    }
}

// ---------------------------------------------------------------------------
extern "C" void kernel_launch(void* const* d_in, const int* in_sizes, int n_in,
                              void* d_out, int out_size)
{
    const float* x    = (const float*)d_in[0];
    const float* wqkv = (const float*)d_in[1];
    const float* wo   = (const float*)d_in[2];
    const float* qw   = (const float*)d_in[3];
    const float* kw   = (const float*)d_in[4];
    const float* fc   = (const float*)d_in[5];
    const float* fs   = (const float*)d_in[6];
    const unsigned char* visraw = (const unsigned char*)d_in[7];
    float* out = (float*)d_out;

    float* qkv;
    __half *qkvh, *attnh, *xh, *wqh, *woh;
    unsigned char* mask;
    cudaGetSymbolAddress((void**)&qkv, g_qkv);
    cudaGetSymbolAddress((void**)&qkvh, g_qkvh);
    cudaGetSymbolAddress((void**)&attnh, g_attnh);
    cudaGetSymbolAddress((void**)&xh, g_xh);
    cudaGetSymbolAddress((void**)&wqh, g_wqh);
    cudaGetSymbolAddress((void**)&woh, g_woh);
    cudaGetSymbolAddress((void**)&mask, g_mask);

    // 0) Mask canonicalization + fp16 conversion of GEMM operands
    mask_prep<<<1, 256>>>(visraw);
    cvt_half<<<2048, 256>>>((const float2*)x, (__half2*)xh, BB * SS * DIMC / 2);
    cvt_half<<<2048, 256>>>((const float2*)wqkv, (__half2*)wqh, QKVC * DIMC / 2);
    cvt_half<<<2048, 256>>>((const float2*)wo, (__half2*)woh, DIMC * DIMC / 2);

    // 1) QKV projection (fp16 mma): [8192,2048] x [3072,2048]^T -> fp32
    cudaFuncSetAttribute(gemm_h, cudaFuncAttributeMaxDynamicSharedMemorySize, HGEMM_SMEM);
    gemm_h<<<dim3(QKVC / 128, (BB * SS) / 128), 256, HGEMM_SMEM>>>(
        xh, wqh, qkv, BB * SS, QKVC, DIMC);

    // 2) RMSNorm + RoPE (q,k) + fp16 conversion (q,k,v)
    norm_rope_h<<<dim3(NH + 2 * NKV, SS, BB), 128>>>(qkv, qkvh, qw, kw, fc, fs);

    // 3) Attention (fp16 mma flash) -> fp16
    cudaFuncSetAttribute(attn_h, cudaFuncAttributeMaxDynamicSharedMemorySize, ATTH_SMEM);
    attn_h<<<dim3(SS / 64, NH / 2, BB), 256, ATTH_SMEM>>>(qkvh, mask, attnh);

    // 4) Output projection (fp16 mma): [8192,2048] x [2048,2048]^T -> fp32
    gemm_h<<<dim3(DIMC / 128, (BB * SS) / 128), 256, HGEMM_SMEM>>>(
        attnh, woh, out, BB * SS, DIMC, DIMC);
}

// round 11
// speedup vs baseline: 8.5159x; 1.0779x over previous
#include <cuda_runtime.h>
#include <cuda_fp16.h>
#include <math.h>
#include <cstdint>

#define BB   4
#define SS   2048
#define DIMC 2048
#define NH   16
#define NKV  4
#define HD   128
#define QKVC 3072
#define EPSF 1.1920928955078125e-07f
#define NEGF -1e30f

// Scratch (device globals: allocation-free per harness rules)
__device__ __half g_qkvh[(size_t)BB * SS * QKVC];   // 48 MB fp16 (gemm1 fused out)
__device__ __half g_attnh[(size_t)BB * SS * DIMC];  // 32 MB fp16 (attn out)
__device__ __half g_xh[(size_t)BB * SS * DIMC];     // 32 MB
__device__ __half g_wqh[(size_t)QKVC * DIMC];       // 12 MB
__device__ __half g_woh[(size_t)DIMC * DIMC];       //  8 MB
__device__ unsigned char g_mask[BB * SS];

// ===========================================================================
// Portable helpers (sm_80-baseline ISA; no 'a'-suffix features)
// ===========================================================================
__device__ __forceinline__ uint32_t smem_u32(const void* p) {
    uint32_t a;
    asm("{ .reg .u64 t; cvta.to.shared.u64 t, %1; cvt.u32.u64 %0, t; }" : "=r"(a) : "l"(p));
    return a;
}
__device__ __forceinline__ void cp16(uint32_t s, const void* g) {
    asm volatile("cp.async.cg.shared.global [%0], [%1], 16;" :: "r"(s), "l"(g));
}
#define CP_COMMIT() asm volatile("cp.async.commit_group;" ::: "memory")
#define CP_WAIT(n)  asm volatile("cp.async.wait_group %0;" :: "n"(n) : "memory")

__device__ __forceinline__ void ldsm4(uint32_t* r, uint32_t a) {
    asm volatile("ldmatrix.sync.aligned.m8n8.x4.shared.b16 {%0,%1,%2,%3}, [%4];"
                 : "=r"(r[0]), "=r"(r[1]), "=r"(r[2]), "=r"(r[3]) : "r"(a));
}
__device__ __forceinline__ void ldsm4t(uint32_t* r, uint32_t a) {
    asm volatile("ldmatrix.sync.aligned.m8n8.x4.trans.shared.b16 {%0,%1,%2,%3}, [%4];"
                 : "=r"(r[0]), "=r"(r[1]), "=r"(r[2]), "=r"(r[3]) : "r"(a));
}
__device__ __forceinline__ void mma_f16(float* c, uint32_t a0, uint32_t a1,
                                        uint32_t a2, uint32_t a3,
                                        uint32_t b0, uint32_t b1) {
    asm volatile(
        "mma.sync.aligned.m16n8k16.row.col.f32.f16.f16.f32 "
        "{%0,%1,%2,%3}, {%4,%5,%6,%7}, {%8,%9}, {%0,%1,%2,%3};"
        : "+f"(c[0]), "+f"(c[1]), "+f"(c[2]), "+f"(c[3])
        : "r"(a0), "r"(a1), "r"(a2), "r"(a3), "r"(b0), "r"(b1));
}

// ===========================================================================
// fp32 -> fp16 conversion (elementwise)
// ===========================================================================
__global__ __launch_bounds__(256) void cvt_half(const float2* __restrict__ in,
                                                __half2* __restrict__ out, int n2)
{
    for (int i = blockIdx.x * 256 + threadIdx.x; i < n2; i += gridDim.x * 256) {
        float2 v = in[i];
        out[i] = __floats2half2_rn(v.x, v.y);
    }
}

// ===========================================================================
// Mask canonicalization (dtype-robust): writes 0/1 bytes into g_mask.
// ===========================================================================
__global__ __launch_bounds__(256) void mask_prep(const unsigned char* __restrict__ raw)
{
    __shared__ int kind;  // 0=int32, 1=bool/u8, 2=float32
    if (threadIdx.x == 0) kind = 0;
    __syncthreads();
    const int NTOK = BB * SS;
    for (int i = threadIdx.x; i < NTOK; i += 256) {
        unsigned char v = raw[i];
        if ((i & 3) == 3 && v == 0x3F) kind = 2;
        else if ((i & 3) != 0 && v != 0) kind = 1;
    }
    __syncthreads();
    int k = kind;
    for (int i = threadIdx.x; i < NTOK; i += 256) {
        unsigned char m;
        if (k == 2)      m = (((const float*)raw)[i] != 0.0f);
        else if (k == 1) m = (raw[i] != 0);
        else             m = (((const int*)raw)[i] != 0);
        g_mask[i] = m;
    }
}

// ===========================================================================
// FP16 mma.sync GEMM. CTA 128x128, K-tile 64 halfs, 3-stage cp.async,
// 8 warps (2x4), warp 64x32, ldmatrix.x4 frags, 2 CTAs/SM.
// MODE 0: C(fp32) plain.  MODE 1: fused per-head RMSNorm+RoPE -> fp16 qkvh
// (n-tile == one head: norm reduction is CTA-local).
// ===========================================================================
#define HROW   72                        // halfs per smem row (64 + 8 pad)
#define HTILE  (128 * HROW)              // halfs per operand tile
#define HSTAGE (2 * HTILE)
#define HGEMM_SMEM (3 * HSTAGE * 2)      // 110592 B

__device__ __forceinline__ void ld_stage_h(uint32_t sb, const __half* gA,
                                           const __half* gB, int K, int kof, int t)
{
    const int cq = t & 7;
    const int r0 = t >> 3;
#pragma unroll
    for (int i = 0; i < 4; i++) {
        const int r = r0 + 32 * i;
        const uint32_t so = (uint32_t)(r * HROW + cq * 8) * 2u;
        cp16(sb + so, gA + (size_t)r * K + kof + cq * 8);
        cp16(sb + HTILE * 2 + so, gB + (size_t)r * K + kof + cq * 8);
    }
}

template <int MODE>
__global__ __launch_bounds__(256, 2) void gemm_h(const __half* __restrict__ A,
                                                 const __half* __restrict__ Bm,
                                                 float* __restrict__ Cf,
                                                 __half* __restrict__ Ch,
                                                 const float* __restrict__ qw,
                                                 const float* __restrict__ kw,
                                                 const float* __restrict__ fcos,
                                                 const float* __restrict__ fsin,
                                                 int M, int N, int K)
{
    extern __shared__ __align__(16) char smc[];
    const uint32_t smb = smem_u32(smc);
    const int t = threadIdx.x;
    const int lane = t & 31;
    const int wid = t >> 5;
    const int wr = wid >> 2;
    const int wc = wid & 3;
    const int g = lane >> 2;
    const int q = lane & 3;
    const int m0 = blockIdx.y * 128;
    const int n0 = blockIdx.x * 128;
    const int NK = K >> 6;

    const __half* gA = A + (size_t)m0 * K;
    const __half* gB = Bm + (size_t)n0 * K;

    float c[4][4][4];
#pragma unroll
    for (int i = 0; i < 4; i++)
#pragma unroll
        for (int j = 0; j < 4; j++)
#pragma unroll
            for (int r = 0; r < 4; r++) c[i][j][r] = 0.f;

#pragma unroll
    for (int s = 0; s < 2; s++) {
        ld_stage_h(smb + s * HSTAGE * 2, gA, gB, K, s * 64, t);
        CP_COMMIT();
    }

    const uint32_t lrow = (uint32_t)(lane & 15);
    const uint32_t lhi  = (uint32_t)(lane >> 4) * 8u;

    for (int kt = 0; kt < NK; kt++) {
        CP_WAIT(1);
        __syncthreads();

        const uint32_t st = smb + (kt % 3) * HSTAGE * 2;
        const uint32_t aB = st + ((wr * 64 + lrow) * HROW + lhi) * 2;
        const uint32_t bB = st + HTILE * 2 + ((wc * 32 + lrow) * HROW + lhi) * 2;

#pragma unroll
        for (int ks = 0; ks < 4; ks++) {
            uint32_t bf[4][2];
#pragma unroll
            for (int j = 0; j < 2; j++) {
                uint32_t r[4];
                ldsm4(r, bB + (uint32_t)(j * 16 * HROW * 2 + ks * 32));
                bf[2 * j][0] = r[0]; bf[2 * j + 1][0] = r[1];
                bf[2 * j][1] = r[2]; bf[2 * j + 1][1] = r[3];
            }
#pragma unroll
            for (int i = 0; i < 4; i++) {
                uint32_t a[4];
                ldsm4(a, aB + (uint32_t)(i * 16 * HROW * 2 + ks * 32));
#pragma unroll
                for (int j = 0; j < 4; j++)
                    mma_f16(c[i][j], a[0], a[1], a[2], a[3], bf[j][0], bf[j][1]);
            }
        }

        const int pf = kt + 2;
        if (pf < NK)
            ld_stage_h(smb + (pf % 3) * HSTAGE * 2, gA, gB, K, pf * 64, t);
        CP_COMMIT();
    }

    if (MODE == 0) {
#pragma unroll
        for (int i = 0; i < 4; i++) {
            const int row = m0 + wr * 64 + i * 16 + g;
#pragma unroll
            for (int j = 0; j < 4; j++) {
                const int col = n0 + wc * 32 + j * 8 + q * 2;
                *(float2*)(Cf + (size_t)row * N + col) = make_float2(c[i][j][0], c[i][j][1]);
                *(float2*)(Cf + (size_t)(row + 8) * N + col) = make_float2(c[i][j][2], c[i][j][3]);
            }
        }
        return;
    }

    // ---- MODE 1: fused per-head RMSNorm + RoPE, fp16 out ----
    const int head = n0 >> 7;                 // 0..23
    const int ht = (head < NH) ? 0 : ((head < NH + NKV) ? 1 : 2);  // q/k/v
    const float* wv = (ht == 0) ? qw : kw;

    __syncthreads();                          // mainloop smem dead for all warps
    float4* rsum = (float4*)smc;              // [128] per-row partials (one per wc)

    // per-row sum of squares: quad reduce, then lane q==0 writes its wc slot
#pragma unroll
    for (int i = 0; i < 4; i++) {
#pragma unroll
        for (int rh = 0; rh < 2; rh++) {
            float p = 0.f;
#pragma unroll
            for (int j = 0; j < 4; j++) {
                float v0 = c[i][j][2 * rh], v1 = c[i][j][2 * rh + 1];
                p += v0 * v0 + v1 * v1;
            }
            p += __shfl_xor_sync(0xffffffffu, p, 1);
            p += __shfl_xor_sync(0xffffffffu, p, 2);
            if (q == 0)
                ((float*)&rsum[wr * 64 + i * 16 + rh * 8 + g])[wc] = p;
        }
    }
    __syncthreads();

#pragma unroll
    for (int i = 0; i < 4; i++) {
#pragma unroll
        for (int rh = 0; rh < 2; rh++) {
            const int lr = wr * 64 + i * 16 + rh * 8 + g;
            float4 rs = rsum[lr];
            const float tot = rs.x + rs.y + rs.z + rs.w;
            const float rn = rsqrtf(tot * (1.f / HD) + EPSF);
            const int tok = m0 + lr;
            const int s = tok & (SS - 1);
            __half* op = Ch + (size_t)tok * QKVC + n0;
#pragma unroll
            for (int j = 0; j < 4; j++) {
                const int col = wc * 32 + j * 8 + 2 * q;
                float v0 = c[i][j][2 * rh], v1 = c[i][j][2 * rh + 1];
                if (ht < 2) {
                    const float xn0 = v0 * rn * wv[col];
                    const float xn1 = v1 * rn * wv[col + 1];
                    const float cs = fcos[s * HD + col];
                    const float sn = fsin[s * HD + col];
                    v0 = xn0 * cs - xn1 * sn;
                    v1 = xn1 * cs + xn0 * sn;
                }
                *(__half2*)(op + col) = __floats2half2_rn(v0, v1);
            }
        }
    }
}

// ===========================================================================
// FP16 flash attention (unchanged from R10-passing version).
// ===========================================================================
#define AKROW 136
#define KTH   (64 * AKROW)
#define STH   (2 * KTH)
#define POH   (2 * STH)
#define PROW  72
#define SVB   ((POH + 128 * PROW) * 2)
#define ATTH_SMEM (SVB + 2 * 64 * 4 + 64)

__device__ __forceinline__ void ld_kv_h(uint32_t sb, const __half* Kg,
                                        const __half* Vg, int t)
{
    const int c = t & 15;
    const int r0 = t >> 4;
#pragma unroll
    for (int i = 0; i < 4; i++) {
        const int r = r0 + 16 * i;
        const uint32_t so = (uint32_t)(r * AKROW + c * 8) * 2u;
        cp16(sb + so, Kg + (size_t)r * QKVC + c * 8);
        cp16(sb + KTH * 2 + so, Vg + (size_t)r * QKVC + c * 8);
    }
}

__global__ __launch_bounds__(256, 1) void attn_h(const __half* __restrict__ qkvh,
                                                 const unsigned char* __restrict__ vis,
                                                 __half* __restrict__ outp)
{
    extern __shared__ __align__(16) char smc[];
    __half* hsm = (__half*)smc;
    const uint32_t smb = smem_u32(smc);
    const int t = threadIdx.x;
    const int lane = t & 31;
    const int w = t >> 5;
    const int g = lane >> 2;
    const int q = lane & 3;
    const int qt = blockIdx.x;
    const int hp = blockIdx.y;
    const int b  = blockIdx.z;
    const int h  = hp * 2 + (w >> 2);
    const int kvh = hp >> 1;
    const int qrow = (w & 3) << 4;

    const size_t tokbase = (size_t)b * SS;
    const unsigned char* visb = vis + tokbase;

    const __half* Qb = qkvh + (tokbase + qt * 64) * QKVC + h * HD;
    const __half* Qg0 = Qb + (size_t)(qrow + g) * QKVC;
    const __half* Qg1 = Qb + (size_t)(qrow + g + 8) * QKVC;
    uint32_t qf[8][4];
#pragma unroll
    for (int kc = 0; kc < 8; kc++) {
        qf[kc][0] = *(const uint32_t*)(Qg0 + kc * 16 + 2 * q);
        qf[kc][1] = *(const uint32_t*)(Qg1 + kc * 16 + 2 * q);
        qf[kc][2] = *(const uint32_t*)(Qg0 + kc * 16 + 8 + 2 * q);
        qf[kc][3] = *(const uint32_t*)(Qg1 + kc * 16 + 8 + 2 * q);
    }

    __half* pwarp = hsm + POH + (16 * w) * PROW;
    float* svb = (float*)(smc + SVB);

    float o[16][4];
#pragma unroll
    for (int nf = 0; nf < 16; nf++)
#pragma unroll
        for (int r = 0; r < 4; r++) o[nf][r] = 0.f;
    float m0p = -INFINITY, m1p = -INFINITY, l0 = 0.f, l1 = 0.f;
    const float scale = 0.08838834764831843f;

    const __half* KB = qkvh + tokbase * QKVC + DIMC + kvh * HD;

#pragma unroll
    for (int s = 0; s < 2; s++) {
        const __half* Kg = KB + (size_t)(s * 64) * QKVC;
        ld_kv_h(smb + s * STH * 2, Kg, Kg + NKV * HD, t);
        if (t < 64) svb[s * 64 + t] = visb[s * 64 + t] ? 0.f : NEGF;
        CP_COMMIT();
    }

    const uint32_t lrow = (uint32_t)(lane & 15);
    const uint32_t lhi  = (uint32_t)(lane >> 4) * 8u;

    for (int kt = 0; kt < SS / 64; kt++) {
        CP_WAIT(1);
        __syncthreads();

        const uint32_t ksb = smb + (kt & 1) * STH * 2;
        const uint32_t vsb = ksb + KTH * 2;
        const float* svp = svb + (kt & 1) * 64;

        float c8[8][4];
#pragma unroll
        for (int f = 0; f < 8; f++)
#pragma unroll
            for (int r = 0; r < 4; r++) c8[f][r] = 0.f;

        const uint32_t kfB = ksb + (lrow * AKROW + lhi) * 2;
#pragma unroll
        for (int kc = 0; kc < 8; kc++) {
#pragma unroll
            for (int fb = 0; fb < 4; fb++) {
                uint32_t r[4];
                ldsm4(r, kfB + (uint32_t)(fb * 16 * AKROW * 2 + kc * 32));
                mma_f16(c8[2 * fb],     qf[kc][0], qf[kc][1], qf[kc][2], qf[kc][3], r[0], r[2]);
                mma_f16(c8[2 * fb + 1], qf[kc][0], qf[kc][1], qf[kc][2], qf[kc][3], r[1], r[3]);
            }
        }

        float rmx0 = -INFINITY, rmx1 = -INFINITY;
#pragma unroll
        for (int f = 0; f < 8; f++) {
            float a0 = svp[8 * f + 2 * q], a1 = svp[8 * f + 2 * q + 1];
            c8[f][0] = c8[f][0] * scale + a0;
            c8[f][1] = c8[f][1] * scale + a1;
            c8[f][2] = c8[f][2] * scale + a0;
            c8[f][3] = c8[f][3] * scale + a1;
            rmx0 = fmaxf(rmx0, fmaxf(c8[f][0], c8[f][1]));
            rmx1 = fmaxf(rmx1, fmaxf(c8[f][2], c8[f][3]));
        }
        rmx0 = fmaxf(rmx0, __shfl_xor_sync(0xffffffffu, rmx0, 1));
        rmx0 = fmaxf(rmx0, __shfl_xor_sync(0xffffffffu, rmx0, 2));
        rmx1 = fmaxf(rmx1, __shfl_xor_sync(0xffffffffu, rmx1, 1));
        rmx1 = fmaxf(rmx1, __shfl_xor_sync(0xffffffffu, rmx1, 2));

        float mn0 = fmaxf(m0p, rmx0), mn1 = fmaxf(m1p, rmx1);
        float al0 = __expf(m0p - mn0), al1 = __expf(m1p - mn1);
        m0p = mn0; m1p = mn1;

        float ps0 = 0.f, ps1 = 0.f;
#pragma unroll
        for (int f = 0; f < 8; f++) {
            float p0 = __expf(c8[f][0] - mn0);
            float p1 = __expf(c8[f][1] - mn0);
            float p2 = __expf(c8[f][2] - mn1);
            float p3 = __expf(c8[f][3] - mn1);
            ps0 += p0 + p1; ps1 += p2 + p3;
            *(__half2*)(pwarp + g * PROW + f * 8 + 2 * q) = __floats2half2_rn(p0, p1);
            *(__half2*)(pwarp + (g + 8) * PROW + f * 8 + 2 * q) = __floats2half2_rn(p2, p3);
        }
        ps0 += __shfl_xor_sync(0xffffffffu, ps0, 1);
        ps0 += __shfl_xor_sync(0xffffffffu, ps0, 2);
        ps1 += __shfl_xor_sync(0xffffffffu, ps1, 1);
        ps1 += __shfl_xor_sync(0xffffffffu, ps1, 2);
        l0 = l0 * al0 + ps0;
        l1 = l1 * al1 + ps1;

#pragma unroll
        for (int nf = 0; nf < 16; nf++) {
            o[nf][0] *= al0; o[nf][1] *= al0;
            o[nf][2] *= al1; o[nf][3] *= al1;
        }
        __syncwarp();

        const uint32_t vfB = vsb + (lrow * AKROW + lhi) * 2;
#pragma unroll
        for (int kc = 0; kc < 4; kc++) {
            uint32_t a0 = *(const uint32_t*)(pwarp + g * PROW + kc * 16 + 2 * q);
            uint32_t a1 = *(const uint32_t*)(pwarp + (g + 8) * PROW + kc * 16 + 2 * q);
            uint32_t a2 = *(const uint32_t*)(pwarp + g * PROW + kc * 16 + 8 + 2 * q);
            uint32_t a3 = *(const uint32_t*)(pwarp + (g + 8) * PROW + kc * 16 + 8 + 2 * q);
#pragma unroll
            for (int db = 0; db < 8; db++) {
                uint32_t r[4];
                ldsm4t(r, vfB + (uint32_t)(kc * 16 * AKROW * 2 + db * 32));
                mma_f16(o[2 * db],     a0, a1, a2, a3, r[0], r[1]);
                mma_f16(o[2 * db + 1], a0, a1, a2, a3, r[2], r[3]);
            }
        }

        __syncthreads();
        const int pf = kt + 2;
        if (pf < SS / 64) {
            const __half* Kg = KB + (size_t)(pf * 64) * QKVC;
            ld_kv_h(smb + (pf & 1) * STH * 2, Kg, Kg + NKV * HD, t);
            if (t < 64) svb[(pf & 1) * 64 + t] = visb[pf * 64 + t] ? 0.f : NEGF;
        }
        CP_COMMIT();
    }

    const int r0 = qt * 64 + qrow + g;
    const int r1 = r0 + 8;
    const float f0 = visb[r0] ? (1.f / l0) : 0.f;
    const float f1 = visb[r1] ? (1.f / l1) : 0.f;
    __half* o0 = outp + (tokbase + r0) * DIMC + h * HD;
    __half* o1 = outp + (tokbase + r1) * DIMC + h * HD;
#pragma unroll
    for (int nf = 0; nf < 16; nf++) {
        *(__half2*)(o0 + nf * 8 + 2 * q) = __floats2half2_rn(o[nf][0] * f0, o[nf][1] * f0);
        *(__half2*)(o1 + nf * 8 + 2 * q) = __floats2half2_rn(o[nf][2] * f1, o[nf][3] * f1);
    }
}

// ---------------------------------------------------------------------------
extern "C" void kernel_launch(void* const* d_in, const int* in_sizes, int n_in,
                              void* d_out, int out_size)
{
    const float* x    = (const float*)d_in[0];
    const float* wqkv = (const float*)d_in[1];
    const float* wo   = (const float*)d_in[2];
    const float* qw   = (const float*)d_in[3];
    const float* kw   = (const float*)d_in[4];
    const float* fc   = (const float*)d_in[5];
    const float* fs   = (const float*)d_in[6];
    const unsigned char* visraw = (const unsigned char*)d_in[7];
    float* out = (float*)d_out;

    __half *qkvh, *attnh, *xh, *wqh, *woh;
    unsigned char* mask;
    cudaGetSymbolAddress((void**)&qkvh, g_qkvh);
    cudaGetSymbolAddress((void**)&attnh, g_attnh);
    cudaGetSymbolAddress((void**)&xh, g_xh);
    cudaGetSymbolAddress((void**)&wqh, g_wqh);
    cudaGetSymbolAddress((void**)&woh, g_woh);
    cudaGetSymbolAddress((void**)&mask, g_mask);

    // 0) Mask canonicalization + fp16 conversion of GEMM operands
    mask_prep<<<1, 256>>>(visraw);
    cvt_half<<<2048, 256>>>((const float2*)x, (__half2*)xh, BB * SS * DIMC / 2);
    cvt_half<<<2048, 256>>>((const float2*)wqkv, (__half2*)wqh, QKVC * DIMC / 2);
    cvt_half<<<2048, 256>>>((const float2*)wo, (__half2*)woh, DIMC * DIMC / 2);

    // 1) QKV projection + fused RMSNorm/RoPE -> fp16 qkvh
    cudaFuncSetAttribute(gemm_h<1>, cudaFuncAttributeMaxDynamicSharedMemorySize, HGEMM_SMEM);
    gemm_h<1><<<dim3(QKVC / 128, (BB * SS) / 128), 256, HGEMM_SMEM>>>(
        xh, wqh, nullptr, qkvh, qw, kw, fc, fs, BB * SS, QKVC, DIMC);

    // 2) Attention (fp16 mma flash) -> fp16
    cudaFuncSetAttribute(attn_h, cudaFuncAttributeMaxDynamicSharedMemorySize, ATTH_SMEM);
    attn_h<<<dim3(SS / 64, NH / 2, BB), 256, ATTH_SMEM>>>(qkvh, mask, attnh);

    // 3) Output projection (fp16 mma) -> fp32 out
    cudaFuncSetAttribute(gemm_h<0>, cudaFuncAttributeMaxDynamicSharedMemorySize, HGEMM_SMEM);
    gemm_h<0><<<dim3(DIMC / 128, (BB * SS) / 128), 256, HGEMM_SMEM>>>(
        attnh, woh, out, nullptr, nullptr, nullptr, nullptr, nullptr,
        BB * SS, DIMC, DIMC);
}

// round 12
// speedup vs baseline: 12.1479x; 1.4265x over previous
#include <cuda_runtime.h>
#include <cuda_fp16.h>
#include <math.h>
#include <cstdint>

#define BB   4
#define SS   2048
#define DIMC 2048
#define NH   16
#define NKV  4
#define HD   128
#define QKVC 3072
#define EPSF 1.1920928955078125e-07f
#define NEGF -1e30f

// Scratch (device globals: allocation-free per harness rules)
__device__ __half g_qkvh[(size_t)BB * SS * QKVC];   // 48 MB fp16 (gemm1 fused out)
__device__ __half g_attnh[(size_t)BB * SS * DIMC];  // 32 MB fp16 (attn out)
__device__ __half g_xh[(size_t)BB * SS * DIMC];     // 32 MB
__device__ __half g_wqh[(size_t)QKVC * DIMC];       // 12 MB
__device__ __half g_woh[(size_t)DIMC * DIMC];       //  8 MB
__device__ unsigned char g_mask[BB * SS];
__device__ int g_vidx[BB * SS];                     // compacted visible token idx
__device__ int g_nvis[BB];                          // visible count per batch

// ===========================================================================
// Portable helpers (sm_80-baseline ISA; no 'a'-suffix features)
// ===========================================================================
__device__ __forceinline__ uint32_t smem_u32(const void* p) {
    uint32_t a;
    asm("{ .reg .u64 t; cvta.to.shared.u64 t, %1; cvt.u32.u64 %0, t; }" : "=r"(a) : "l"(p));
    return a;
}
__device__ __forceinline__ void cp16(uint32_t s, const void* g) {
    asm volatile("cp.async.cg.shared.global [%0], [%1], 16;" :: "r"(s), "l"(g));
}
#define CP_COMMIT() asm volatile("cp.async.commit_group;" ::: "memory")
#define CP_WAIT(n)  asm volatile("cp.async.wait_group %0;" :: "n"(n) : "memory")

__device__ __forceinline__ void ldsm4(uint32_t* r, uint32_t a) {
    asm volatile("ldmatrix.sync.aligned.m8n8.x4.shared.b16 {%0,%1,%2,%3}, [%4];"
                 : "=r"(r[0]), "=r"(r[1]), "=r"(r[2]), "=r"(r[3]) : "r"(a));
}
__device__ __forceinline__ void ldsm4t(uint32_t* r, uint32_t a) {
    asm volatile("ldmatrix.sync.aligned.m8n8.x4.trans.shared.b16 {%0,%1,%2,%3}, [%4];"
                 : "=r"(r[0]), "=r"(r[1]), "=r"(r[2]), "=r"(r[3]) : "r"(a));
}
__device__ __forceinline__ void mma_f16(float* c, uint32_t a0, uint32_t a1,
                                        uint32_t a2, uint32_t a3,
                                        uint32_t b0, uint32_t b1) {
    asm volatile(
        "mma.sync.aligned.m16n8k16.row.col.f32.f16.f16.f32 "
        "{%0,%1,%2,%3}, {%4,%5,%6,%7}, {%8,%9}, {%0,%1,%2,%3};"
        : "+f"(c[0]), "+f"(c[1]), "+f"(c[2]), "+f"(c[3])
        : "r"(a0), "r"(a1), "r"(a2), "r"(a3), "r"(b0), "r"(b1));
}

// ===========================================================================
// fp32 -> fp16 conversion (elementwise)
// ===========================================================================
__global__ __launch_bounds__(256) void cvt_half(const float2* __restrict__ in,
                                                __half2* __restrict__ out, int n2)
{
    for (int i = blockIdx.x * 256 + threadIdx.x; i < n2; i += gridDim.x * 256) {
        float2 v = in[i];
        out[i] = __floats2half2_rn(v.x, v.y);
    }
}

// Zero attn buffer (invisible tokens stay zero; visible overwritten by attn)
__global__ __launch_bounds__(256) void zero_h(float4* __restrict__ p, int n8)
{
    float4 z = make_float4(0.f, 0.f, 0.f, 0.f);
    for (int i = blockIdx.x * 256 + threadIdx.x; i < n8; i += gridDim.x * 256)
        p[i] = z;
}

// ===========================================================================
// Mask canonicalization (dtype-robust): writes 0/1 bytes into g_mask.
// ===========================================================================
__global__ __launch_bounds__(256) void mask_prep(const unsigned char* __restrict__ raw)
{
    __shared__ int kind;  // 0=int32, 1=bool/u8, 2=float32
    if (threadIdx.x == 0) kind = 0;
    __syncthreads();
    const int NTOK = BB * SS;
    for (int i = threadIdx.x; i < NTOK; i += 256) {
        unsigned char v = raw[i];
        if ((i & 3) == 3 && v == 0x3F) kind = 2;
        else if ((i & 3) != 0 && v != 0) kind = 1;
    }
    __syncthreads();
    int k = kind;
    for (int i = threadIdx.x; i < NTOK; i += 256) {
        unsigned char m;
        if (k == 2)      m = (((const float*)raw)[i] != 0.0f);
        else if (k == 1) m = (raw[i] != 0);
        else             m = (((const int*)raw)[i] != 0);
        g_mask[i] = m;
    }
}

// ===========================================================================
// Visible-token compaction: per batch, block scan of g_mask -> g_vidx/g_nvis.
// ===========================================================================
__global__ __launch_bounds__(1024) void compact_mask()
{
    __shared__ int sa[1024], sb[1024];
    const int b = blockIdx.x, t = threadIdx.x;
    const unsigned char* mb = g_mask + b * SS;
    const int m0 = mb[2 * t], m1 = mb[2 * t + 1];
    sa[t] = m0 + m1;
    __syncthreads();
    int* src = sa;
    int* dst = sb;
    for (int off = 1; off < 1024; off <<= 1) {
        dst[t] = src[t] + ((t >= off) ? src[t - off] : 0);
        __syncthreads();
        int* tmp = src; src = dst; dst = tmp;
    }
    const int incl = src[t];
    int ex = incl - (m0 + m1);
    if (m0) g_vidx[b * SS + ex] = 2 * t, ex++;
    if (m1) g_vidx[b * SS + ex] = 2 * t + 1;
    if (t == 1023) g_nvis[b] = incl;
}

// ===========================================================================
// FP16 mma.sync GEMM. CTA 128x128, K-tile 64 halfs, 3-stage cp.async,
// 8 warps (2x4), warp 64x32, ldmatrix.x4 frags, 2 CTAs/SM.
// MODE 0: C(fp32) plain.  MODE 1: fused per-head RMSNorm+RoPE -> fp16 qkvh.
// ===========================================================================
#define HROW   72
#define HTILE  (128 * HROW)
#define HSTAGE (2 * HTILE)
#define HGEMM_SMEM (3 * HSTAGE * 2)      // 110592 B

__device__ __forceinline__ void ld_stage_h(uint32_t sb, const __half* gA,
                                           const __half* gB, int K, int kof, int t)
{
    const int cq = t & 7;
    const int r0 = t >> 3;
#pragma unroll
    for (int i = 0; i < 4; i++) {
        const int r = r0 + 32 * i;
        const uint32_t so = (uint32_t)(r * HROW + cq * 8) * 2u;
        cp16(sb + so, gA + (size_t)r * K + kof + cq * 8);
        cp16(sb + HTILE * 2 + so, gB + (size_t)r * K + kof + cq * 8);
    }
}

template <int MODE>
__global__ __launch_bounds__(256, 2) void gemm_h(const __half* __restrict__ A,
                                                 const __half* __restrict__ Bm,
                                                 float* __restrict__ Cf,
                                                 __half* __restrict__ Ch,
                                                 const float* __restrict__ qw,
                                                 const float* __restrict__ kw,
                                                 const float* __restrict__ fcos,
                                                 const float* __restrict__ fsin,
                                                 int M, int N, int K)
{
    extern __shared__ __align__(16) char smc[];
    const uint32_t smb = smem_u32(smc);
    const int t = threadIdx.x;
    const int lane = t & 31;
    const int wid = t >> 5;
    const int wr = wid >> 2;
    const int wc = wid & 3;
    const int g = lane >> 2;
    const int q = lane & 3;
    const int m0 = blockIdx.y * 128;
    const int n0 = blockIdx.x * 128;
    const int NK = K >> 6;

    const __half* gA = A + (size_t)m0 * K;
    const __half* gB = Bm + (size_t)n0 * K;

    float c[4][4][4];
#pragma unroll
    for (int i = 0; i < 4; i++)
#pragma unroll
        for (int j = 0; j < 4; j++)
#pragma unroll
            for (int r = 0; r < 4; r++) c[i][j][r] = 0.f;

#pragma unroll
    for (int s = 0; s < 2; s++) {
        ld_stage_h(smb + s * HSTAGE * 2, gA, gB, K, s * 64, t);
        CP_COMMIT();
    }

    const uint32_t lrow = (uint32_t)(lane & 15);
    const uint32_t lhi  = (uint32_t)(lane >> 4) * 8u;

    for (int kt = 0; kt < NK; kt++) {
        CP_WAIT(1);
        __syncthreads();

        const uint32_t st = smb + (kt % 3) * HSTAGE * 2;
        const uint32_t aB = st + ((wr * 64 + lrow) * HROW + lhi) * 2;
        const uint32_t bB = st + HTILE * 2 + ((wc * 32 + lrow) * HROW + lhi) * 2;

#pragma unroll
        for (int ks = 0; ks < 4; ks++) {
            uint32_t bf[4][2];
#pragma unroll
            for (int j = 0; j < 2; j++) {
                uint32_t r[4];
                ldsm4(r, bB + (uint32_t)(j * 16 * HROW * 2 + ks * 32));
                bf[2 * j][0] = r[0]; bf[2 * j + 1][0] = r[1];
                bf[2 * j][1] = r[2]; bf[2 * j + 1][1] = r[3];
            }
#pragma unroll
            for (int i = 0; i < 4; i++) {
                uint32_t a[4];
                ldsm4(a, aB + (uint32_t)(i * 16 * HROW * 2 + ks * 32));
#pragma unroll
                for (int j = 0; j < 4; j++)
                    mma_f16(c[i][j], a[0], a[1], a[2], a[3], bf[j][0], bf[j][1]);
            }
        }

        const int pf = kt + 2;
        if (pf < NK)
            ld_stage_h(smb + (pf % 3) * HSTAGE * 2, gA, gB, K, pf * 64, t);
        CP_COMMIT();
    }

    if (MODE == 0) {
#pragma unroll
        for (int i = 0; i < 4; i++) {
            const int row = m0 + wr * 64 + i * 16 + g;
#pragma unroll
            for (int j = 0; j < 4; j++) {
                const int col = n0 + wc * 32 + j * 8 + q * 2;
                *(float2*)(Cf + (size_t)row * N + col) = make_float2(c[i][j][0], c[i][j][1]);
                *(float2*)(Cf + (size_t)(row + 8) * N + col) = make_float2(c[i][j][2], c[i][j][3]);
            }
        }
        return;
    }

    // ---- MODE 1: fused per-head RMSNorm + RoPE, fp16 out ----
    const int head = n0 >> 7;
    const int ht = (head < NH) ? 0 : ((head < NH + NKV) ? 1 : 2);
    const float* wv = (ht == 0) ? qw : kw;

    __syncthreads();
    float4* rsum = (float4*)smc;

#pragma unroll
    for (int i = 0; i < 4; i++) {
#pragma unroll
        for (int rh = 0; rh < 2; rh++) {
            float p = 0.f;
#pragma unroll
            for (int j = 0; j < 4; j++) {
                float v0 = c[i][j][2 * rh], v1 = c[i][j][2 * rh + 1];
                p += v0 * v0 + v1 * v1;
            }
            p += __shfl_xor_sync(0xffffffffu, p, 1);
            p += __shfl_xor_sync(0xffffffffu, p, 2);
            if (q == 0)
                ((float*)&rsum[wr * 64 + i * 16 + rh * 8 + g])[wc] = p;
        }
    }
    __syncthreads();

#pragma unroll
    for (int i = 0; i < 4; i++) {
#pragma unroll
        for (int rh = 0; rh < 2; rh++) {
            const int lr = wr * 64 + i * 16 + rh * 8 + g;
            float4 rs = rsum[lr];
            const float tot = rs.x + rs.y + rs.z + rs.w;
            const float rn = rsqrtf(tot * (1.f / HD) + EPSF);
            const int tok = m0 + lr;
            const int s = tok & (SS - 1);
            __half* op = Ch + (size_t)tok * QKVC + n0;
#pragma unroll
            for (int j = 0; j < 4; j++) {
                const int col = wc * 32 + j * 8 + 2 * q;
                float v0 = c[i][j][2 * rh], v1 = c[i][j][2 * rh + 1];
                if (ht < 2) {
                    const float xn0 = v0 * rn * wv[col];
                    const float xn1 = v1 * rn * wv[col + 1];
                    const float cs = fcos[s * HD + col];
                    const float sn = fsin[s * HD + col];
                    v0 = xn0 * cs - xn1 * sn;
                    v1 = xn1 * cs + xn0 * sn;
                }
                *(__half2*)(op + col) = __floats2half2_rn(v0, v1);
            }
        }
    }
}

// ===========================================================================
// FP16 flash attention over COMPACTED visible tokens.
// CTA: 2 q-heads x 64 compacted queries, shared kv head. Dynamic tile count
// from g_nvis; gathered Q/K/V rows via g_vidx; only last key tile masked.
// ===========================================================================
#define AKROW 136
#define KTH   (64 * AKROW)
#define STH   (2 * KTH)
#define POH   (2 * STH)
#define PROW  72
#define SVB   ((POH + 128 * PROW) * 2)
#define ATTH_SMEM (SVB + 2 * 64 * 4 + 64)

__device__ __forceinline__ void ld_kv_g(uint32_t sb, const __half* KBbase,
                                        const int* vidx_b, int nv, int tile, int t)
{
    const int c = t & 15;
    const int r0 = t >> 4;
#pragma unroll
    for (int i = 0; i < 4; i++) {
        const int r = r0 + 16 * i;
        int j = tile * 64 + r;
        const int tok = vidx_b[j < nv ? j : nv - 1];
        const __half* Kg = KBbase + (size_t)tok * QKVC;
        const uint32_t so = (uint32_t)(r * AKROW + c * 8) * 2u;
        cp16(sb + so, Kg + c * 8);
        cp16(sb + KTH * 2 + so, Kg + NKV * HD + c * 8);
    }
}

__global__ __launch_bounds__(256, 1) void attn_h(const __half* __restrict__ qkvh,
                                                 const int* __restrict__ vidx,
                                                 const int* __restrict__ nvis,
                                                 __half* __restrict__ outp)
{
    const int qt = blockIdx.x;
    const int b  = blockIdx.z;
    const int nv = nvis[b];
    const int ntile = (nv + 63) >> 6;
    if (qt >= ntile) return;

    extern __shared__ __align__(16) char smc[];
    __half* hsm = (__half*)smc;
    const uint32_t smb = smem_u32(smc);
    const int t = threadIdx.x;
    const int lane = t & 31;
    const int w = t >> 5;
    const int g = lane >> 2;
    const int q = lane & 3;
    const int hp = blockIdx.y;
    const int h  = hp * 2 + (w >> 2);
    const int kvh = hp >> 1;
    const int qrow = (w & 3) << 4;

    const size_t tokbase = (size_t)b * SS;
    const int* vidx_b = vidx + b * SS;

    // Gathered Q fragments
    const int j0 = qt * 64 + qrow + g;
    const int j1 = j0 + 8;
    const int tok0 = vidx_b[j0 < nv ? j0 : nv - 1];
    const int tok1 = vidx_b[j1 < nv ? j1 : nv - 1];
    const __half* Qg0 = qkvh + (tokbase + tok0) * QKVC + h * HD;
    const __half* Qg1 = qkvh + (tokbase + tok1) * QKVC + h * HD;
    uint32_t qf[8][4];
#pragma unroll
    for (int kc = 0; kc < 8; kc++) {
        qf[kc][0] = *(const uint32_t*)(Qg0 + kc * 16 + 2 * q);
        qf[kc][1] = *(const uint32_t*)(Qg1 + kc * 16 + 2 * q);
        qf[kc][2] = *(const uint32_t*)(Qg0 + kc * 16 + 8 + 2 * q);
        qf[kc][3] = *(const uint32_t*)(Qg1 + kc * 16 + 8 + 2 * q);
    }

    __half* pwarp = hsm + POH + (16 * w) * PROW;
    float* svb = (float*)(smc + SVB);

    float o[16][4];
#pragma unroll
    for (int nf = 0; nf < 16; nf++)
#pragma unroll
        for (int r = 0; r < 4; r++) o[nf][r] = 0.f;
    float m0p = -INFINITY, m1p = -INFINITY, l0 = 0.f, l1 = 0.f;
    const float scale = 0.08838834764831843f;

    const __half* KBbase = qkvh + tokbase * QKVC + DIMC + kvh * HD;

#pragma unroll
    for (int s = 0; s < 2; s++) {
        if (s < ntile) {
            ld_kv_g(smb + s * STH * 2, KBbase, vidx_b, nv, s, t);
            if (t < 64) svb[s * 64 + t] = (s * 64 + t < nv) ? 0.f : NEGF;
        }
        CP_COMMIT();
    }

    const uint32_t lrow = (uint32_t)(lane & 15);
    const uint32_t lhi  = (uint32_t)(lane >> 4) * 8u;

    for (int kt = 0; kt < ntile; kt++) {
        CP_WAIT(1);
        __syncthreads();

        const uint32_t ksb = smb + (kt & 1) * STH * 2;
        const uint32_t vsb = ksb + KTH * 2;
        const float* svp = svb + (kt & 1) * 64;

        float c8[8][4];
#pragma unroll
        for (int f = 0; f < 8; f++)
#pragma unroll
            for (int r = 0; r < 4; r++) c8[f][r] = 0.f;

        const uint32_t kfB = ksb + (lrow * AKROW + lhi) * 2;
#pragma unroll
        for (int kc = 0; kc < 8; kc++) {
#pragma unroll
            for (int fb = 0; fb < 4; fb++) {
                uint32_t r[4];
                ldsm4(r, kfB + (uint32_t)(fb * 16 * AKROW * 2 + kc * 32));
                mma_f16(c8[2 * fb],     qf[kc][0], qf[kc][1], qf[kc][2], qf[kc][3], r[0], r[2]);
                mma_f16(c8[2 * fb + 1], qf[kc][0], qf[kc][1], qf[kc][2], qf[kc][3], r[1], r[3]);
            }
        }

        float rmx0 = -INFINITY, rmx1 = -INFINITY;
#pragma unroll
        for (int f = 0; f < 8; f++) {
            float a0 = svp[8 * f + 2 * q], a1 = svp[8 * f + 2 * q + 1];
            c8[f][0] = c8[f][0] * scale + a0;
            c8[f][1] = c8[f][1] * scale + a1;
            c8[f][2] = c8[f][2] * scale + a0;
            c8[f][3] = c8[f][3] * scale + a1;
            rmx0 = fmaxf(rmx0, fmaxf(c8[f][0], c8[f][1]));
            rmx1 = fmaxf(rmx1, fmaxf(c8[f][2], c8[f][3]));
        }
        rmx0 = fmaxf(rmx0, __shfl_xor_sync(0xffffffffu, rmx0, 1));
        rmx0 = fmaxf(rmx0, __shfl_xor_sync(0xffffffffu, rmx0, 2));
        rmx1 = fmaxf(rmx1, __shfl_xor_sync(0xffffffffu, rmx1, 1));
        rmx1 = fmaxf(rmx1, __shfl_xor_sync(0xffffffffu, rmx1, 2));

        float mn0 = fmaxf(m0p, rmx0), mn1 = fmaxf(m1p, rmx1);
        float al0 = __expf(m0p - mn0), al1 = __expf(m1p - mn1);
        m0p = mn0; m1p = mn1;

        float ps0 = 0.f, ps1 = 0.f;
#pragma unroll
        for (int f = 0; f < 8; f++) {
            float p0 = __expf(c8[f][0] - mn0);
            float p1 = __expf(c8[f][1] - mn0);
            float p2 = __expf(c8[f][2] - mn1);
            float p3 = __expf(c8[f][3] - mn1);
            ps0 += p0 + p1; ps1 += p2 + p3;
            *(__half2*)(pwarp + g * PROW + f * 8 + 2 * q) = __floats2half2_rn(p0, p1);
            *(__half2*)(pwarp + (g + 8) * PROW + f * 8 + 2 * q) = __floats2half2_rn(p2, p3);
        }
        ps0 += __shfl_xor_sync(0xffffffffu, ps0, 1);
        ps0 += __shfl_xor_sync(0xffffffffu, ps0, 2);
        ps1 += __shfl_xor_sync(0xffffffffu, ps1, 1);
        ps1 += __shfl_xor_sync(0xffffffffu, ps1, 2);
        l0 = l0 * al0 + ps0;
        l1 = l1 * al1 + ps1;

#pragma unroll
        for (int nf = 0; nf < 16; nf++) {
            o[nf][0] *= al0; o[nf][1] *= al0;
            o[nf][2] *= al1; o[nf][3] *= al1;
        }
        __syncwarp();

        const uint32_t vfB = vsb + (lrow * AKROW + lhi) * 2;
#pragma unroll
        for (int kc = 0; kc < 4; kc++) {
            uint32_t a0 = *(const uint32_t*)(pwarp + g * PROW + kc * 16 + 2 * q);
            uint32_t a1 = *(const uint32_t*)(pwarp + (g + 8) * PROW + kc * 16 + 2 * q);
            uint32_t a2 = *(const uint32_t*)(pwarp + g * PROW + kc * 16 + 8 + 2 * q);
            uint32_t a3 = *(const uint32_t*)(pwarp + (g + 8) * PROW + kc * 16 + 8 + 2 * q);
#pragma unroll
            for (int db = 0; db < 8; db++) {
                uint32_t r[4];
                ldsm4t(r, vfB + (uint32_t)(kc * 16 * AKROW * 2 + db * 32));
                mma_f16(o[2 * db],     a0, a1, a2, a3, r[0], r[1]);
                mma_f16(o[2 * db + 1], a0, a1, a2, a3, r[2], r[3]);
            }
        }

        __syncthreads();
        const int pf = kt + 2;
        if (pf < ntile) {
            ld_kv_g(smb + (pf & 1) * STH * 2, KBbase, vidx_b, nv, pf, t);
            if (t < 64) svb[(pf & 1) * 64 + t] = (pf * 64 + t < nv) ? 0.f : NEGF;
        }
        CP_COMMIT();
    }

    // ---- epilogue: scatter normalized rows to their original tokens ----
    if (j0 < nv) {
        const float f0 = 1.f / l0;
        __half* o0 = outp + (tokbase + tok0) * DIMC + h * HD;
#pragma unroll
        for (int nf = 0; nf < 16; nf++)
            *(__half2*)(o0 + nf * 8 + 2 * q) = __floats2half2_rn(o[nf][0] * f0, o[nf][1] * f0);
    }
    if (j1 < nv) {
        const float f1 = 1.f / l1;
        __half* o1 = outp + (tokbase + tok1) * DIMC + h * HD;
#pragma unroll
        for (int nf = 0; nf < 16; nf++)
            *(__half2*)(o1 + nf * 8 + 2 * q) = __floats2half2_rn(o[nf][2] * f1, o[nf][3] * f1);
    }
}

// ---------------------------------------------------------------------------
extern "C" void kernel_launch(void* const* d_in, const int* in_sizes, int n_in,
                              void* d_out, int out_size)
{
    const float* x    = (const float*)d_in[0];
    const float* wqkv = (const float*)d_in[1];
    const float* wo   = (const float*)d_in[2];
    const float* qw   = (const float*)d_in[3];
    const float* kw   = (const float*)d_in[4];
    const float* fc   = (const float*)d_in[5];
    const float* fs   = (const float*)d_in[6];
    const unsigned char* visraw = (const unsigned char*)d_in[7];
    float* out = (float*)d_out;

    __half *qkvh, *attnh, *xh, *wqh, *woh;
    int *vidx, *nvis;
    cudaGetSymbolAddress((void**)&qkvh, g_qkvh);
    cudaGetSymbolAddress((void**)&attnh, g_attnh);
    cudaGetSymbolAddress((void**)&xh, g_xh);
    cudaGetSymbolAddress((void**)&wqh, g_wqh);
    cudaGetSymbolAddress((void**)&woh, g_woh);
    cudaGetSymbolAddress((void**)&vidx, g_vidx);
    cudaGetSymbolAddress((void**)&nvis, g_nvis);

    // 0) Mask canonicalization, compaction, operand conversion, output zero
    mask_prep<<<1, 256>>>(visraw);
    compact_mask<<<BB, 1024>>>();
    cvt_half<<<2048, 256>>>((const float2*)x, (__half2*)xh, BB * SS * DIMC / 2);
    cvt_half<<<2048, 256>>>((const float2*)wqkv, (__half2*)wqh, QKVC * DIMC / 2);
    cvt_half<<<2048, 256>>>((const float2*)wo, (__half2*)woh, DIMC * DIMC / 2);
    zero_h<<<2048, 256>>>((float4*)attnh, BB * SS * DIMC / 8);

    // 1) QKV projection + fused RMSNorm/RoPE -> fp16 qkvh
    cudaFuncSetAttribute(gemm_h<1>, cudaFuncAttributeMaxDynamicSharedMemorySize, HGEMM_SMEM);
    gemm_h<1><<<dim3(QKVC / 128, (BB * SS) / 128), 256, HGEMM_SMEM>>>(
        xh, wqh, nullptr, qkvh, qw, kw, fc, fs, BB * SS, QKVC, DIMC);

    // 2) Attention over compacted visible tokens -> fp16 (scattered)
    cudaFuncSetAttribute(attn_h, cudaFuncAttributeMaxDynamicSharedMemorySize, ATTH_SMEM);
    attn_h<<<dim3(SS / 64, NH / 2, BB), 256, ATTH_SMEM>>>(qkvh, vidx, nvis, attnh);

    // 3) Output projection (fp16 mma) -> fp32 out
    cudaFuncSetAttribute(gemm_h<0>, cudaFuncAttributeMaxDynamicSharedMemorySize, HGEMM_SMEM);
    gemm_h<0><<<dim3(DIMC / 128, (BB * SS) / 128), 256, HGEMM_SMEM>>>(
        attnh, woh, out, nullptr, nullptr, nullptr, nullptr, nullptr,
        BB * SS, DIMC, DIMC);
}

// round 14
// speedup vs baseline: 17.1471x; 1.4115x over previous
#include <cuda_runtime.h>
#include <cuda_fp16.h>
#include <math.h>
#include <cstdint>

#define BB   4
#define SS   2048
#define DIMC 2048
#define NH   16
#define NKV  4
#define HD   128
#define QKVC 3072
#define EPSF 1.1920928955078125e-07f
#define NEGF -1e30f

// Scratch (device globals: allocation-free per harness rules)
__device__ __half g_qkvh[(size_t)BB * SS * QKVC];   // fp16, COMPACTED rows
__device__ __half g_attnh[(size_t)BB * SS * DIMC];  // fp16, COMPACTED rows
__device__ __half g_xh[(size_t)BB * SS * DIMC];
__device__ __half g_wqh[(size_t)QKVC * DIMC];
__device__ __half g_woh[(size_t)DIMC * DIMC];
__device__ unsigned char g_mask[BB * SS];
__device__ int g_vidx[BB * SS];                     // compacted visible token idx
__device__ int g_nvis[BB];                          // visible count per batch

// ===========================================================================
// Portable helpers (sm_80-baseline ISA; no 'a'-suffix features)
// ===========================================================================
__device__ __forceinline__ uint32_t smem_u32(const void* p) {
    uint32_t a;
    asm("{ .reg .u64 t; cvta.to.shared.u64 t, %1; cvt.u32.u64 %0, t; }" : "=r"(a) : "l"(p));
    return a;
}
__device__ __forceinline__ void cp16(uint32_t s, const void* g) {
    asm volatile("cp.async.cg.shared.global [%0], [%1], 16;" :: "r"(s), "l"(g));
}
#define CP_COMMIT() asm volatile("cp.async.commit_group;" ::: "memory")
#define CP_WAIT(n)  asm volatile("cp.async.wait_group %0;" :: "n"(n) : "memory")

__device__ __forceinline__ void ldsm4(uint32_t* r, uint32_t a) {
    asm volatile("ldmatrix.sync.aligned.m8n8.x4.shared.b16 {%0,%1,%2,%3}, [%4];"
                 : "=r"(r[0]), "=r"(r[1]), "=r"(r[2]), "=r"(r[3]) : "r"(a));
}
__device__ __forceinline__ void ldsm4t(uint32_t* r, uint32_t a) {
    asm volatile("ldmatrix.sync.aligned.m8n8.x4.trans.shared.b16 {%0,%1,%2,%3}, [%4];"
                 : "=r"(r[0]), "=r"(r[1]), "=r"(r[2]), "=r"(r[3]) : "r"(a));
}
__device__ __forceinline__ void mma_f16(float* c, uint32_t a0, uint32_t a1,
                                        uint32_t a2, uint32_t a3,
                                        uint32_t b0, uint32_t b1) {
    asm volatile(
        "mma.sync.aligned.m16n8k16.row.col.f32.f16.f16.f32 "
        "{%0,%1,%2,%3}, {%4,%5,%6,%7}, {%8,%9}, {%0,%1,%2,%3};"
        : "+f"(c[0]), "+f"(c[1]), "+f"(c[2]), "+f"(c[3])
        : "r"(a0), "r"(a1), "r"(a2), "r"(a3), "r"(b0), "r"(b1));
}

// ===========================================================================
// fp32 -> fp16 conversion / zero
// ===========================================================================
__global__ __launch_bounds__(256) void cvt_half(const float2* __restrict__ in,
                                                __half2* __restrict__ out, int n2)
{
    for (int i = blockIdx.x * 256 + threadIdx.x; i < n2; i += gridDim.x * 256) {
        float2 v = in[i];
        out[i] = __floats2half2_rn(v.x, v.y);
    }
}
__global__ __launch_bounds__(256) void zero_f(float4* __restrict__ p, int n4)
{
    float4 z = make_float4(0.f, 0.f, 0.f, 0.f);
    for (int i = blockIdx.x * 256 + threadIdx.x; i < n4; i += gridDim.x * 256)
        p[i] = z;
}

// ===========================================================================
// Mask canonicalization (dtype-robust): writes 0/1 bytes into g_mask.
// ===========================================================================
__global__ __launch_bounds__(256) void mask_prep(const unsigned char* __restrict__ raw)
{
    __shared__ int kind;  // 0=int32, 1=bool/u8, 2=float32
    if (threadIdx.x == 0) kind = 0;
    __syncthreads();
    const int NTOK = BB * SS;
    for (int i = threadIdx.x; i < NTOK; i += 256) {
        unsigned char v = raw[i];
        if ((i & 3) == 3 && v == 0x3F) kind = 2;
        else if ((i & 3) != 0 && v != 0) kind = 1;
    }
    __syncthreads();
    int k = kind;
    for (int i = threadIdx.x; i < NTOK; i += 256) {
        unsigned char m;
        if (k == 2)      m = (((const float*)raw)[i] != 0.0f);
        else if (k == 1) m = (raw[i] != 0);
        else             m = (((const int*)raw)[i] != 0);
        g_mask[i] = m;
    }
}

// ===========================================================================
// Visible-token compaction: per batch, block scan of g_mask -> g_vidx/g_nvis.
// ===========================================================================
__global__ __launch_bounds__(1024) void compact_mask()
{
    __shared__ int sa[1024], sb[1024];
    const int b = blockIdx.x, t = threadIdx.x;
    const unsigned char* mb = g_mask + b * SS;
    const int m0 = mb[2 * t], m1 = mb[2 * t + 1];
    sa[t] = m0 + m1;
    __syncthreads();
    int* src = sa;
    int* dst = sb;
    for (int off = 1; off < 1024; off <<= 1) {
        dst[t] = src[t] + ((t >= off) ? src[t - off] : 0);
        __syncthreads();
        int* tmp = src; src = dst; dst = tmp;
    }
    const int incl = src[t];
    int ex = incl - (m0 + m1);
    if (m0) g_vidx[b * SS + ex] = 2 * t, ex++;
    if (m1) g_vidx[b * SS + ex] = 2 * t + 1;
    if (t == 1023) g_nvis[b] = incl;
}

// ===========================================================================
// FP16 mma.sync GEMM over COMPACTED visible rows.
// grid.y = BB*16 M-tiles; CTA exits if its tile >= ceil(nvis[b]/128).
// MODE 1 (gemm1): A rows gathered via vidx; fused per-head RMSNorm+RoPE
//                 (RoPE position = original token pos); fp16 out, compacted.
// MODE 0 (gemm2): A rows read compacted directly; fp32 epilogue scattered
//                 to original token rows (guarded j < nv).
// ===========================================================================
#define HROW   72
#define HTILE  (128 * HROW)
#define HSTAGE (2 * HTILE)
#define HGEMM_SMEM (3 * HSTAGE * 2)      // 110592 B

template <int MODE>
__global__ __launch_bounds__(256, 2) void gemm_h(const __half* __restrict__ A,
                                                 const __half* __restrict__ Bm,
                                                 float* __restrict__ Cf,
                                                 __half* __restrict__ Ch,
                                                 const float* __restrict__ qw,
                                                 const float* __restrict__ kw,
                                                 const float* __restrict__ fcos,
                                                 const float* __restrict__ fsin,
                                                 const int* __restrict__ vidx,
                                                 const int* __restrict__ nvis,
                                                 int N, int K)
{
    const int b  = blockIdx.y >> 4;
    const int lt = blockIdx.y & 15;
    const int nv = nvis[b];
    if (lt * 128 >= nv) return;

    extern __shared__ __align__(16) char smc[];
    const uint32_t smb = smem_u32(smc);
    const int t = threadIdx.x;
    const int lane = t & 31;
    const int wid = t >> 5;
    const int wr = wid >> 2;
    const int wc = wid & 3;
    const int g = lane >> 2;
    const int q = lane & 3;
    const int n0 = blockIdx.x * 128;
    const int NK = K >> 6;
    const int m0l = lt * 128;                    // local compacted row base
    const int* vidx_b = vidx + b * SS;

    // Per-thread A-row pointers (4 rows each, fixed across K)
    const int cq = t & 7;
    const int r0 = t >> 3;
    const __half* aptr[4];
#pragma unroll
    for (int i = 0; i < 4; i++) {
        const int r = r0 + 32 * i;
        int j = m0l + r;
        if (MODE == 1) {                          // gather original x rows
            if (j >= nv) j = nv - 1;
            aptr[i] = A + ((size_t)b * SS + vidx_b[j]) * K + cq * 8;
        } else {                                  // compacted attnh rows
            aptr[i] = A + ((size_t)b * SS + j) * K + cq * 8;
        }
    }
    const __half* gB = Bm + (size_t)n0 * K + cq * 8;

    float c[4][4][4];
#pragma unroll
    for (int i = 0; i < 4; i++)
#pragma unroll
        for (int j = 0; j < 4; j++)
#pragma unroll
            for (int r = 0; r < 4; r++) c[i][j][r] = 0.f;

#pragma unroll
    for (int s = 0; s < 2; s++) {
        const uint32_t sb = smb + s * HSTAGE * 2;
#pragma unroll
        for (int i = 0; i < 4; i++) {
            const int r = r0 + 32 * i;
            const uint32_t so = (uint32_t)(r * HROW + cq * 8) * 2u;
            cp16(sb + so, aptr[i] + s * 64);
            cp16(sb + HTILE * 2 + so, gB + (size_t)r * K + s * 64);
        }
        CP_COMMIT();
    }

    const uint32_t lrow = (uint32_t)(lane & 15);
    const uint32_t lhi  = (uint32_t)(lane >> 4) * 8u;

    for (int kt = 0; kt < NK; kt++) {
        CP_WAIT(1);
        __syncthreads();

        const uint32_t st = smb + (kt % 3) * HSTAGE * 2;
        const uint32_t aB = st + ((wr * 64 + lrow) * HROW + lhi) * 2;
        const uint32_t bB = st + HTILE * 2 + ((wc * 32 + lrow) * HROW + lhi) * 2;

#pragma unroll
        for (int ks = 0; ks < 4; ks++) {
            uint32_t bf[4][2];
#pragma unroll
            for (int j = 0; j < 2; j++) {
                uint32_t r[4];
                ldsm4(r, bB + (uint32_t)(j * 16 * HROW * 2 + ks * 32));
                bf[2 * j][0] = r[0]; bf[2 * j + 1][0] = r[1];
                bf[2 * j][1] = r[2]; bf[2 * j + 1][1] = r[3];
            }
#pragma unroll
            for (int i = 0; i < 4; i++) {
                uint32_t a[4];
                ldsm4(a, aB + (uint32_t)(i * 16 * HROW * 2 + ks * 32));
#pragma unroll
                for (int j = 0; j < 4; j++)
                    mma_f16(c[i][j], a[0], a[1], a[2], a[3], bf[j][0], bf[j][1]);
            }
        }

        const int pf = kt + 2;
        if (pf < NK) {
            const uint32_t sb = smb + (pf % 3) * HSTAGE * 2;
#pragma unroll
            for (int i = 0; i < 4; i++) {
                const int r = r0 + 32 * i;
                const uint32_t so = (uint32_t)(r * HROW + cq * 8) * 2u;
                cp16(sb + so, aptr[i] + pf * 64);
                cp16(sb + HTILE * 2 + so, gB + (size_t)r * K + pf * 64);
            }
        }
        CP_COMMIT();
    }

    if (MODE == 0) {
        // scatter fp32 rows to original token positions
#pragma unroll
        for (int i = 0; i < 4; i++) {
#pragma unroll
            for (int rh = 0; rh < 2; rh++) {
                const int j = m0l + wr * 64 + i * 16 + rh * 8 + g;
                if (j >= nv) continue;
                const int tok = vidx_b[j];
                float* op = Cf + ((size_t)b * SS + tok) * N + n0;
#pragma unroll
                for (int jj = 0; jj < 4; jj++) {
                    const int col = wc * 32 + jj * 8 + q * 2;
                    *(float2*)(op + col) =
                        make_float2(c[i][jj][2 * rh], c[i][jj][2 * rh + 1]);
                }
            }
        }
        return;
    }

    // ---- MODE 1: fused per-head RMSNorm + RoPE, fp16 compacted out ----
    const int head = n0 >> 7;
    const int ht = (head < NH) ? 0 : ((head < NH + NKV) ? 1 : 2);
    const float* wv = (ht == 0) ? qw : kw;

    __syncthreads();
    float4* rsum = (float4*)smc;

#pragma unroll
    for (int i = 0; i < 4; i++) {
#pragma unroll
        for (int rh = 0; rh < 2; rh++) {
            float p = 0.f;
#pragma unroll
            for (int j = 0; j < 4; j++) {
                float v0 = c[i][j][2 * rh], v1 = c[i][j][2 * rh + 1];
                p += v0 * v0 + v1 * v1;
            }
            p += __shfl_xor_sync(0xffffffffu, p, 1);
            p += __shfl_xor_sync(0xffffffffu, p, 2);
            if (q == 0)
                ((float*)&rsum[wr * 64 + i * 16 + rh * 8 + g])[wc] = p;
        }
    }
    __syncthreads();

#pragma unroll
    for (int i = 0; i < 4; i++) {
#pragma unroll
        for (int rh = 0; rh < 2; rh++) {
            const int lr = wr * 64 + i * 16 + rh * 8 + g;
            float4 rs = rsum[lr];
            const float tot = rs.x + rs.y + rs.z + rs.w;
            const float rn = rsqrtf(tot * (1.f / HD) + EPSF);
            const int j = m0l + lr;
            const int jc = (j < nv) ? j : nv - 1;
            const int s = vidx_b[jc];             // original position for RoPE
            __half* op = Ch + ((size_t)b * SS + j) * QKVC + n0;
#pragma unroll
            for (int jj = 0; jj < 4; jj++) {
                const int col = wc * 32 + jj * 8 + 2 * q;
                float v0 = c[i][jj][2 * rh], v1 = c[i][jj][2 * rh + 1];
                if (ht < 2) {
                    const float xn0 = v0 * rn * wv[col];
                    const float xn1 = v1 * rn * wv[col + 1];
                    const float cs = fcos[s * HD + col];
                    const float sn = fsin[s * HD + col];
                    v0 = xn0 * cs - xn1 * sn;
                    v1 = xn1 * cs + xn0 * sn;
                }
                *(__half2*)(op + col) = __floats2half2_rn(v0, v1);
            }
        }
    }
}

// ===========================================================================
// FP16 flash attention over COMPACTED rows (direct indexing, no gather).
// CTA: 2 q-heads x 64 compacted queries, shared kv head. Writes compacted
// attnh rows (guarded j < nv). Padded tail keys masked by index.
// ===========================================================================
#define AKROW 136
#define KTH   (64 * AKROW)
#define STH   (2 * KTH)
#define POH   (2 * STH)
#define PROW  72
#define SVB   ((POH + 128 * PROW) * 2)
#define ATTH_SMEM (SVB + 2 * 64 * 4 + 64)

__device__ __forceinline__ void ld_kv_c(uint32_t sb, const __half* KBbase, int tile, int t)
{
    const int c = t & 15;
    const int r0 = t >> 4;
#pragma unroll
    for (int i = 0; i < 4; i++) {
        const int r = r0 + 16 * i;
        const __half* Kg = KBbase + (size_t)(tile * 64 + r) * QKVC;
        const uint32_t so = (uint32_t)(r * AKROW + c * 8) * 2u;
        cp16(sb + so, Kg + c * 8);
        cp16(sb + KTH * 2 + so, Kg + NKV * HD + c * 8);
    }
}

__global__ __launch_bounds__(256, 1) void attn_h(const __half* __restrict__ qkvh,
                                                 const int* __restrict__ nvis,
                                                 __half* __restrict__ outp)
{
    const int qt = blockIdx.x;
    const int b  = blockIdx.z;
    const int nv = nvis[b];
    const int ntile = (nv + 63) >> 6;
    if (qt >= ntile) return;

    extern __shared__ __align__(16) char smc[];
    __half* hsm = (__half*)smc;
    const uint32_t smb = smem_u32(smc);
    const int t = threadIdx.x;
    const int lane = t & 31;
    const int w = t >> 5;
    const int g = lane >> 2;
    const int q = lane & 3;
    const int hp = blockIdx.y;
    const int h  = hp * 2 + (w >> 2);
    const int kvh = hp >> 1;
    const int qrow = (w & 3) << 4;

    const size_t tokbase = (size_t)b * SS;

    // Q fragments: direct compacted rows
    const int j0 = qt * 64 + qrow + g;
    const int j1 = j0 + 8;
    const int jc0 = (j0 < nv) ? j0 : nv - 1;
    const int jc1 = (j1 < nv) ? j1 : nv - 1;
    const __half* Qg0 = qkvh + (tokbase + jc0) * QKVC + h * HD;
    const __half* Qg1 = qkvh + (tokbase + jc1) * QKVC + h * HD;
    uint32_t qf[8][4];
#pragma unroll
    for (int kc = 0; kc < 8; kc++) {
        qf[kc][0] = *(const uint32_t*)(Qg0 + kc * 16 + 2 * q);
        qf[kc][1] = *(const uint32_t*)(Qg1 + kc * 16 + 2 * q);
        qf[kc][2] = *(const uint32_t*)(Qg0 + kc * 16 + 8 + 2 * q);
        qf[kc][3] = *(const uint32_t*)(Qg1 + kc * 16 + 8 + 2 * q);
    }

    __half* pwarp = hsm + POH + (16 * w) * PROW;
    float* svb = (float*)(smc + SVB);

    float o[16][4];
#pragma unroll
    for (int nf = 0; nf < 16; nf++)
#pragma unroll
        for (int r = 0; r < 4; r++) o[nf][r] = 0.f;
    float m0p = -INFINITY, m1p = -INFINITY, l0 = 0.f, l1 = 0.f;
    const float scale = 0.08838834764831843f;

    const __half* KBbase = qkvh + tokbase * QKVC + DIMC + kvh * HD;

#pragma unroll
    for (int s = 0; s < 2; s++) {
        if (s < ntile) {
            ld_kv_c(smb + s * STH * 2, KBbase, s, t);
            if (t < 64) svb[s * 64 + t] = (s * 64 + t < nv) ? 0.f : NEGF;
        }
        CP_COMMIT();
    }

    const uint32_t lrow = (uint32_t)(lane & 15);
    const uint32_t lhi  = (uint32_t)(lane >> 4) * 8u;

    for (int kt = 0; kt < ntile; kt++) {
        CP_WAIT(1);
        __syncthreads();

        const uint32_t ksb = smb + (kt & 1) * STH * 2;
        const uint32_t vsb = ksb + KTH * 2;
        const float* svp = svb + (kt & 1) * 64;

        float c8[8][4];
#pragma unroll
        for (int f = 0; f < 8; f++)
#pragma unroll
            for (int r = 0; r < 4; r++) c8[f][r] = 0.f;

        const uint32_t kfB = ksb + (lrow * AKROW + lhi) * 2;
#pragma unroll
        for (int kc = 0; kc < 8; kc++) {
#pragma unroll
            for (int fb = 0; fb < 4; fb++) {
                uint32_t r[4];
                ldsm4(r, kfB + (uint32_t)(fb * 16 * AKROW * 2 + kc * 32));
                mma_f16(c8[2 * fb],     qf[kc][0], qf[kc][1], qf[kc][2], qf[kc][3], r[0], r[2]);
                mma_f16(c8[2 * fb + 1], qf[kc][0], qf[kc][1], qf[kc][2], qf[kc][3], r[1], r[3]);
            }
        }

        float rmx0 = -INFINITY, rmx1 = -INFINITY;
#pragma unroll
        for (int f = 0; f < 8; f++) {
            float a0 = svp[8 * f + 2 * q], a1 = svp[8 * f + 2 * q + 1];
            c8[f][0] = c8[f][0] * scale + a0;
            c8[f][1] = c8[f][1] * scale + a1;
            c8[f][2] = c8[f][2] * scale + a0;
            c8[f][3] = c8[f][3] * scale + a1;
            rmx0 = fmaxf(rmx0, fmaxf(c8[f][0], c8[f][1]));
            rmx1 = fmaxf(rmx1, fmaxf(c8[f][2], c8[f][3]));
        }
        rmx0 = fmaxf(rmx0, __shfl_xor_sync(0xffffffffu, rmx0, 1));
        rmx0 = fmaxf(rmx0, __shfl_xor_sync(0xffffffffu, rmx0, 2));
        rmx1 = fmaxf(rmx1, __shfl_xor_sync(0xffffffffu, rmx1, 1));
        rmx1 = fmaxf(rmx1, __shfl_xor_sync(0xffffffffu, rmx1, 2));

        float mn0 = fmaxf(m0p, rmx0), mn1 = fmaxf(m1p, rmx1);
        float al0 = __expf(m0p - mn0), al1 = __expf(m1p - mn1);
        m0p = mn0; m1p = mn1;

        float ps0 = 0.f, ps1 = 0.f;
#pragma unroll
        for (int f = 0; f < 8; f++) {
            float p0 = __expf(c8[f][0] - mn0);
            float p1 = __expf(c8[f][1] - mn0);
            float p2 = __expf(c8[f][2] - mn1);
            float p3 = __expf(c8[f][3] - mn1);
            ps0 += p0 + p1; ps1 += p2 + p3;
            *(__half2*)(pwarp + g * PROW + f * 8 + 2 * q) = __floats2half2_rn(p0, p1);
            *(__half2*)(pwarp + (g + 8) * PROW + f * 8 + 2 * q) = __floats2half2_rn(p2, p3);
        }
        ps0 += __shfl_xor_sync(0xffffffffu, ps0, 1);
        ps0 += __shfl_xor_sync(0xffffffffu, ps0, 2);
        ps1 += __shfl_xor_sync(0xffffffffu, ps1, 1);
        ps1 += __shfl_xor_sync(0xffffffffu, ps1, 2);
        l0 = l0 * al0 + ps0;
        l1 = l1 * al1 + ps1;

#pragma unroll
        for (int nf = 0; nf < 16; nf++) {
            o[nf][0] *= al0; o[nf][1] *= al0;
            o[nf][2] *= al1; o[nf][3] *= al1;
        }
        __syncwarp();

        const uint32_t vfB = vsb + (lrow * AKROW + lhi) * 2;
#pragma unroll
        for (int kc = 0; kc < 4; kc++) {
            uint32_t a0 = *(const uint32_t*)(pwarp + g * PROW + kc * 16 + 2 * q);
            uint32_t a1 = *(const uint32_t*)(pwarp + (g + 8) * PROW + kc * 16 + 2 * q);
            uint32_t a2 = *(const uint32_t*)(pwarp + g * PROW + kc * 16 + 8 + 2 * q);
            uint32_t a3 = *(const uint32_t*)(pwarp + (g + 8) * PROW + kc * 16 + 8 + 2 * q);
#pragma unroll
            for (int db = 0; db < 8; db++) {
                uint32_t r[4];
                ldsm4t(r, vfB + (uint32_t)(kc * 16 * AKROW * 2 + db * 32));
                mma_f16(o[2 * db],     a0, a1, a2, a3, r[0], r[1]);
                mma_f16(o[2 * db + 1], a0, a1, a2, a3, r[2], r[3]);
            }
        }

        __syncthreads();
        const int pf = kt + 2;
        if (pf < ntile) {
            ld_kv_c(smb + (pf & 1) * STH * 2, KBbase, pf, t);
            if (t < 64) svb[(pf & 1) * 64 + t] = (pf * 64 + t < nv) ? 0.f : NEGF;
        }
        CP_COMMIT();
    }

    // ---- epilogue: write compacted attnh rows ----
    if (j0 < nv) {
        const float f0 = 1.f / l0;
        __half* o0 = outp + (tokbase + j0) * DIMC + h * HD;
#pragma unroll
        for (int nf = 0; nf < 16; nf++)
            *(__half2*)(o0 + nf * 8 + 2 * q) = __floats2half2_rn(o[nf][0] * f0, o[nf][1] * f0);
    }
    if (j1 < nv) {
        const float f1 = 1.f / l1;
        __half* o1 = outp + (tokbase + j1) * DIMC + h * HD;
#pragma unroll
        for (int nf = 0; nf < 16; nf++)
            *(__half2*)(o1 + nf * 8 + 2 * q) = __floats2half2_rn(o[nf][2] * f1, o[nf][3] * f1);
    }
}

// ---------------------------------------------------------------------------
extern "C" void kernel_launch(void* const* d_in, const int* in_sizes, int n_in,
                              void* d_out, int out_size)
{
    const float* x    = (const float*)d_in[0];
    const float* wqkv = (const float*)d_in[1];
    const float* wo   = (const float*)d_in[2];
    const float* qw   = (const float*)d_in[3];
    const float* kw   = (const float*)d_in[4];
    const float* fc   = (const float*)d_in[5];
    const float* fs   = (const float*)d_in[6];
    const unsigned char* visraw = (const unsigned char*)d_in[7];
    float* out = (float*)d_out;

    __half *qkvh, *attnh, *xh, *wqh, *woh;
    int *vidx, *nvis;
    cudaGetSymbolAddress((void**)&qkvh, g_qkvh);
    cudaGetSymbolAddress((void**)&attnh, g_attnh);
    cudaGetSymbolAddress((void**)&xh, g_xh);
    cudaGetSymbolAddress((void**)&wqh, g_wqh);
    cudaGetSymbolAddress((void**)&woh, g_woh);
    cudaGetSymbolAddress((void**)&vidx, g_vidx);
    cudaGetSymbolAddress((void**)&nvis, g_nvis);

    // 0) Mask canonicalization, compaction, operand conversion, output zero
    mask_prep<<<1, 256>>>(visraw);
    compact_mask<<<BB, 1024>>>();
    cvt_half<<<2048, 256>>>((const float2*)x, (__half2*)xh, BB * SS * DIMC / 2);
    cvt_half<<<2048, 256>>>((const float2*)wqkv, (__half2*)wqh, QKVC * DIMC / 2);
    cvt_half<<<2048, 256>>>((const float2*)wo, (__half2*)woh, DIMC * DIMC / 2);
    zero_f<<<2048, 256>>>((float4*)out, BB * SS * DIMC / 4);

    // 1) QKV projection over visible rows + fused RMSNorm/RoPE -> compacted qkvh
    cudaFuncSetAttribute(gemm_h<1>, cudaFuncAttributeMaxDynamicSharedMemorySize, HGEMM_SMEM);
    gemm_h<1><<<dim3(QKVC / 128, BB * 16), 256, HGEMM_SMEM>>>(
        xh, wqh, nullptr, qkvh, qw, kw, fc, fs, vidx, nvis, QKVC, DIMC);

    // 2) Attention over compacted rows -> compacted attnh
    cudaFuncSetAttribute(attn_h, cudaFuncAttributeMaxDynamicSharedMemorySize, ATTH_SMEM);
    attn_h<<<dim3(SS / 64, NH / 2, BB), 256, ATTH_SMEM>>>(qkvh, nvis, attnh);

    // 3) Output projection over visible rows -> scattered fp32 out
    cudaFuncSetAttribute(gemm_h<0>, cudaFuncAttributeMaxDynamicSharedMemorySize, HGEMM_SMEM);
    gemm_h<0><<<dim3(DIMC / 128, BB * 16), 256, HGEMM_SMEM>>>(
        attnh, woh, out, nullptr, nullptr, nullptr, nullptr, nullptr,
        vidx, nvis, DIMC, DIMC);
}

// round 15
// speedup vs baseline: 17.4871x; 1.0198x over previous
#include <cuda_runtime.h>
#include <cuda_fp16.h>
#include <math.h>
#include <cstdint>

#define BB   4
#define SS   2048
#define DIMC 2048
#define NH   16
#define NKV  4
#define HD   128
#define QKVC 3072
#define EPSF 1.1920928955078125e-07f
#define NEGF -1e30f

// Scratch (device globals: allocation-free per harness rules)
__device__ __half g_qkvh[(size_t)BB * SS * QKVC];   // fp16, COMPACTED rows
__device__ __half g_attnh[(size_t)BB * SS * DIMC];  // fp16, COMPACTED rows
__device__ __half g_xh[(size_t)BB * SS * DIMC];
__device__ __half g_wqh[(size_t)QKVC * DIMC];
__device__ __half g_woh[(size_t)DIMC * DIMC];
__device__ unsigned char g_mask[BB * SS];
__device__ int g_vidx[BB * SS];                     // compacted visible token idx
__device__ int g_nvis[BB];                          // visible count per batch

// ===========================================================================
// Portable helpers (sm_80-baseline ISA; no 'a'-suffix features)
// ===========================================================================
__device__ __forceinline__ uint32_t smem_u32(const void* p) {
    uint32_t a;
    asm("{ .reg .u64 t; cvta.to.shared.u64 t, %1; cvt.u32.u64 %0, t; }" : "=r"(a) : "l"(p));
    return a;
}
__device__ __forceinline__ void cp16(uint32_t s, const void* g) {
    asm volatile("cp.async.cg.shared.global [%0], [%1], 16;" :: "r"(s), "l"(g));
}
#define CP_COMMIT() asm volatile("cp.async.commit_group;" ::: "memory")
#define CP_WAIT(n)  asm volatile("cp.async.wait_group %0;" :: "n"(n) : "memory")

__device__ __forceinline__ void ldsm4(uint32_t* r, uint32_t a) {
    asm volatile("ldmatrix.sync.aligned.m8n8.x4.shared.b16 {%0,%1,%2,%3}, [%4];"
                 : "=r"(r[0]), "=r"(r[1]), "=r"(r[2]), "=r"(r[3]) : "r"(a));
}
__device__ __forceinline__ void ldsm4t(uint32_t* r, uint32_t a) {
    asm volatile("ldmatrix.sync.aligned.m8n8.x4.trans.shared.b16 {%0,%1,%2,%3}, [%4];"
                 : "=r"(r[0]), "=r"(r[1]), "=r"(r[2]), "=r"(r[3]) : "r"(a));
}
__device__ __forceinline__ void mma_f16(float* c, uint32_t a0, uint32_t a1,
                                        uint32_t a2, uint32_t a3,
                                        uint32_t b0, uint32_t b1) {
    asm volatile(
        "mma.sync.aligned.m16n8k16.row.col.f32.f16.f16.f32 "
        "{%0,%1,%2,%3}, {%4,%5,%6,%7}, {%8,%9}, {%0,%1,%2,%3};"
        : "+f"(c[0]), "+f"(c[1]), "+f"(c[2]), "+f"(c[3])
        : "r"(a0), "r"(a1), "r"(a2), "r"(a3), "r"(b0), "r"(b1));
}

// ===========================================================================
// Fused prep 1: mask canonicalization + per-batch visible compaction.
// grid = BB, 1024 threads. Dtype detected per batch slice (2048 entries).
// ===========================================================================
__global__ __launch_bounds__(1024) void prep_mask(const unsigned char* __restrict__ raw)
{
    __shared__ int kind;  // 0=int32, 1=bool/u8, 2=float32
    __shared__ int sa[1024], sb[1024];
    const int b = blockIdx.x, t = threadIdx.x;

    if (t == 0) kind = 0;
    __syncthreads();
    // detect dtype over this batch's slice assuming widest (4B) stride window
    const unsigned char* slice = raw + (size_t)b * SS;      // at least SS bytes valid
    for (int i = t; i < SS; i += 1024) {
        unsigned char v = raw[(size_t)b * SS + i];          // byte-granularity probe
        (void)v;
    }
    // probe the full plausible extents: treat raw as byte stream of the whole
    // mask buffer; detection uses global indices so all layouts are covered.
    for (int i = t; i < BB * SS; i += 1024) {
        unsigned char v = raw[i];
        if ((i & 3) == 3 && v == 0x3F) kind = 2;
        else if ((i & 3) != 0 && v != 0) kind = 1;
    }
    __syncthreads();
    const int k = kind;

    // canonicalize this batch's 2048 entries (2 per thread) + write g_mask
    int m0, m1;
    {
        const int i0 = b * SS + 2 * t, i1 = i0 + 1;
        if (k == 2)      { m0 = (((const float*)raw)[i0] != 0.0f); m1 = (((const float*)raw)[i1] != 0.0f); }
        else if (k == 1) { m0 = (raw[i0] != 0); m1 = (raw[i1] != 0); }
        else             { m0 = (((const int*)raw)[i0] != 0); m1 = (((const int*)raw)[i1] != 0); }
        g_mask[i0] = (unsigned char)m0;
        g_mask[i1] = (unsigned char)m1;
    }
    (void)slice;

    // inclusive block scan over pair-sums
    sa[t] = m0 + m1;
    __syncthreads();
    int* src = sa;
    int* dst = sb;
    for (int off = 1; off < 1024; off <<= 1) {
        dst[t] = src[t] + ((t >= off) ? src[t - off] : 0);
        __syncthreads();
        int* tmp = src; src = dst; dst = tmp;
    }
    const int incl = src[t];
    int ex = incl - (m0 + m1);
    if (m0) g_vidx[b * SS + ex] = 2 * t, ex++;
    if (m1) g_vidx[b * SS + ex] = 2 * t + 1;
    if (t == 1023) g_nvis[b] = incl;
}

// ===========================================================================
// Fused prep 2: fp32->fp16 of x, wqkv, wo in one grid-stride kernel.
// ===========================================================================
#define N2_X  (BB * SS * DIMC / 2)
#define N2_WQ (QKVC * DIMC / 2)
#define N2_WO (DIMC * DIMC / 2)
__global__ __launch_bounds__(256) void cvt_all(const float2* __restrict__ x,
                                               const float2* __restrict__ wq,
                                               const float2* __restrict__ wo,
                                               __half2* __restrict__ xh,
                                               __half2* __restrict__ wqh,
                                               __half2* __restrict__ woh)
{
    const int total = N2_X + N2_WQ + N2_WO;
    for (int i = blockIdx.x * 256 + threadIdx.x; i < total; i += gridDim.x * 256) {
        float2 v;
        __half2* o;
        int j;
        if (i < N2_X)                { j = i; v = x[j]; o = xh + j; }
        else if (i < N2_X + N2_WQ)   { j = i - N2_X; v = wq[j]; o = wqh + j; }
        else                         { j = i - N2_X - N2_WQ; v = wo[j]; o = woh + j; }
        *o = __floats2half2_rn(v.x, v.y);
    }
}

// ===========================================================================
// Fused prep 3: zero ONLY invisible token rows of the fp32 output.
// (visible rows are fully overwritten by gemm2's scatter epilogue)
// ===========================================================================
__global__ __launch_bounds__(256) void zero_inv(float4* __restrict__ out)
{
    // 8192 rows x 512 float4; one thread handles 4 float4 of a row-chunk
    const int CH = DIMC / 4;  // 512 float4 per row
    for (int i = blockIdx.x * 256 + threadIdx.x; i < BB * SS * (CH / 4); i += gridDim.x * 256) {
        const int row = i / (CH / 4);
        if (g_mask[row]) continue;
        const int c0 = (i % (CH / 4)) * 4;
        float4 z = make_float4(0.f, 0.f, 0.f, 0.f);
        float4* p = out + (size_t)row * CH + c0;
        p[0] = z; p[1] = z; p[2] = z; p[3] = z;
    }
}

// ===========================================================================
// FP16 mma.sync GEMM over COMPACTED visible rows (unchanged from R14).
// MODE 1 (gemm1): gathered A rows; fused RMSNorm+RoPE; fp16 compacted out.
// MODE 0 (gemm2): compacted A rows; fp32 epilogue scattered to token rows.
// ===========================================================================
#define HROW   72
#define HTILE  (128 * HROW)
#define HSTAGE (2 * HTILE)
#define HGEMM_SMEM (3 * HSTAGE * 2)      // 110592 B

template <int MODE>
__global__ __launch_bounds__(256, 2) void gemm_h(const __half* __restrict__ A,
                                                 const __half* __restrict__ Bm,
                                                 float* __restrict__ Cf,
                                                 __half* __restrict__ Ch,
                                                 const float* __restrict__ qw,
                                                 const float* __restrict__ kw,
                                                 const float* __restrict__ fcos,
                                                 const float* __restrict__ fsin,
                                                 const int* __restrict__ vidx,
                                                 const int* __restrict__ nvis,
                                                 int N, int K)
{
    const int b  = blockIdx.y >> 4;
    const int lt = blockIdx.y & 15;
    const int nv = nvis[b];
    if (lt * 128 >= nv) return;

    extern __shared__ __align__(16) char smc[];
    const uint32_t smb = smem_u32(smc);
    const int t = threadIdx.x;
    const int lane = t & 31;
    const int wid = t >> 5;
    const int wr = wid >> 2;
    const int wc = wid & 3;
    const int g = lane >> 2;
    const int q = lane & 3;
    const int n0 = blockIdx.x * 128;
    const int NK = K >> 6;
    const int m0l = lt * 128;
    const int* vidx_b = vidx + b * SS;

    const int cq = t & 7;
    const int r0 = t >> 3;
    const __half* aptr[4];
#pragma unroll
    for (int i = 0; i < 4; i++) {
        const int r = r0 + 32 * i;
        int j = m0l + r;
        if (MODE == 1) {
            if (j >= nv) j = nv - 1;
            aptr[i] = A + ((size_t)b * SS + vidx_b[j]) * K + cq * 8;
        } else {
            aptr[i] = A + ((size_t)b * SS + j) * K + cq * 8;
        }
    }
    const __half* gB = Bm + (size_t)n0 * K + cq * 8;

    float c[4][4][4];
#pragma unroll
    for (int i = 0; i < 4; i++)
#pragma unroll
        for (int j = 0; j < 4; j++)
#pragma unroll
            for (int r = 0; r < 4; r++) c[i][j][r] = 0.f;

#pragma unroll
    for (int s = 0; s < 2; s++) {
        const uint32_t sb = smb + s * HSTAGE * 2;
#pragma unroll
        for (int i = 0; i < 4; i++) {
            const int r = r0 + 32 * i;
            const uint32_t so = (uint32_t)(r * HROW + cq * 8) * 2u;
            cp16(sb + so, aptr[i] + s * 64);
            cp16(sb + HTILE * 2 + so, gB + (size_t)r * K + s * 64);
        }
        CP_COMMIT();
    }

    const uint32_t lrow = (uint32_t)(lane & 15);
    const uint32_t lhi  = (uint32_t)(lane >> 4) * 8u;

    for (int kt = 0; kt < NK; kt++) {
        CP_WAIT(1);
        __syncthreads();

        const uint32_t st = smb + (kt % 3) * HSTAGE * 2;
        const uint32_t aB = st + ((wr * 64 + lrow) * HROW + lhi) * 2;
        const uint32_t bB = st + HTILE * 2 + ((wc * 32 + lrow) * HROW + lhi) * 2;

#pragma unroll
        for (int ks = 0; ks < 4; ks++) {
            uint32_t bf[4][2];
#pragma unroll
            for (int j = 0; j < 2; j++) {
                uint32_t r[4];
                ldsm4(r, bB + (uint32_t)(j * 16 * HROW * 2 + ks * 32));
                bf[2 * j][0] = r[0]; bf[2 * j + 1][0] = r[1];
                bf[2 * j][1] = r[2]; bf[2 * j + 1][1] = r[3];
            }
#pragma unroll
            for (int i = 0; i < 4; i++) {
                uint32_t a[4];
                ldsm4(a, aB + (uint32_t)(i * 16 * HROW * 2 + ks * 32));
#pragma unroll
                for (int j = 0; j < 4; j++)
                    mma_f16(c[i][j], a[0], a[1], a[2], a[3], bf[j][0], bf[j][1]);
            }
        }

        const int pf = kt + 2;
        if (pf < NK) {
            const uint32_t sb = smb + (pf % 3) * HSTAGE * 2;
#pragma unroll
            for (int i = 0; i < 4; i++) {
                const int r = r0 + 32 * i;
                const uint32_t so = (uint32_t)(r * HROW + cq * 8) * 2u;
                cp16(sb + so, aptr[i] + pf * 64);
                cp16(sb + HTILE * 2 + so, gB + (size_t)r * K + pf * 64);
            }
        }
        CP_COMMIT();
    }

    if (MODE == 0) {
#pragma unroll
        for (int i = 0; i < 4; i++) {
#pragma unroll
            for (int rh = 0; rh < 2; rh++) {
                const int j = m0l + wr * 64 + i * 16 + rh * 8 + g;
                if (j >= nv) continue;
                const int tok = vidx_b[j];
                float* op = Cf + ((size_t)b * SS + tok) * N + n0;
#pragma unroll
                for (int jj = 0; jj < 4; jj++) {
                    const int col = wc * 32 + jj * 8 + q * 2;
                    *(float2*)(op + col) =
                        make_float2(c[i][jj][2 * rh], c[i][jj][2 * rh + 1]);
                }
            }
        }
        return;
    }

    // ---- MODE 1: fused per-head RMSNorm + RoPE, fp16 compacted out ----
    const int head = n0 >> 7;
    const int ht = (head < NH) ? 0 : ((head < NH + NKV) ? 1 : 2);
    const float* wv = (ht == 0) ? qw : kw;

    __syncthreads();
    float4* rsum = (float4*)smc;

#pragma unroll
    for (int i = 0; i < 4; i++) {
#pragma unroll
        for (int rh = 0; rh < 2; rh++) {
            float p = 0.f;
#pragma unroll
            for (int j = 0; j < 4; j++) {
                float v0 = c[i][j][2 * rh], v1 = c[i][j][2 * rh + 1];
                p += v0 * v0 + v1 * v1;
            }
            p += __shfl_xor_sync(0xffffffffu, p, 1);
            p += __shfl_xor_sync(0xffffffffu, p, 2);
            if (q == 0)
                ((float*)&rsum[wr * 64 + i * 16 + rh * 8 + g])[wc] = p;
        }
    }
    __syncthreads();

#pragma unroll
    for (int i = 0; i < 4; i++) {
#pragma unroll
        for (int rh = 0; rh < 2; rh++) {
            const int lr = wr * 64 + i * 16 + rh * 8 + g;
            float4 rs = rsum[lr];
            const float tot = rs.x + rs.y + rs.z + rs.w;
            const float rn = rsqrtf(tot * (1.f / HD) + EPSF);
            const int j = m0l + lr;
            const int jc = (j < nv) ? j : nv - 1;
            const int s = vidx_b[jc];
            __half* op = Ch + ((size_t)b * SS + j) * QKVC + n0;
#pragma unroll
            for (int jj = 0; jj < 4; jj++) {
                const int col = wc * 32 + jj * 8 + 2 * q;
                float v0 = c[i][jj][2 * rh], v1 = c[i][jj][2 * rh + 1];
                if (ht < 2) {
                    const float xn0 = v0 * rn * wv[col];
                    const float xn1 = v1 * rn * wv[col + 1];
                    const float cs = fcos[s * HD + col];
                    const float sn = fsin[s * HD + col];
                    v0 = xn0 * cs - xn1 * sn;
                    v1 = xn1 * cs + xn0 * sn;
                }
                *(__half2*)(op + col) = __floats2half2_rn(v0, v1);
            }
        }
    }
}

// ===========================================================================
// FP16 flash attention over COMPACTED rows (unchanged from R14).
// ===========================================================================
#define AKROW 136
#define KTH   (64 * AKROW)
#define STH   (2 * KTH)
#define POH   (2 * STH)
#define PROW  72
#define SVB   ((POH + 128 * PROW) * 2)
#define ATTH_SMEM (SVB + 2 * 64 * 4 + 64)

__device__ __forceinline__ void ld_kv_c(uint32_t sb, const __half* KBbase, int tile, int t)
{
    const int c = t & 15;
    const int r0 = t >> 4;
#pragma unroll
    for (int i = 0; i < 4; i++) {
        const int r = r0 + 16 * i;
        const __half* Kg = KBbase + (size_t)(tile * 64 + r) * QKVC;
        const uint32_t so = (uint32_t)(r * AKROW + c * 8) * 2u;
        cp16(sb + so, Kg + c * 8);
        cp16(sb + KTH * 2 + so, Kg + NKV * HD + c * 8);
    }
}

__global__ __launch_bounds__(256, 1) void attn_h(const __half* __restrict__ qkvh,
                                                 const int* __restrict__ nvis,
                                                 __half* __restrict__ outp)
{
    const int qt = blockIdx.x;
    const int b  = blockIdx.z;
    const int nv = nvis[b];
    const int ntile = (nv + 63) >> 6;
    if (qt >= ntile) return;

    extern __shared__ __align__(16) char smc[];
    __half* hsm = (__half*)smc;
    const uint32_t smb = smem_u32(smc);
    const int t = threadIdx.x;
    const int lane = t & 31;
    const int w = t >> 5;
    const int g = lane >> 2;
    const int q = lane & 3;
    const int hp = blockIdx.y;
    const int h  = hp * 2 + (w >> 2);
    const int kvh = hp >> 1;
    const int qrow = (w & 3) << 4;

    const size_t tokbase = (size_t)b * SS;

    const int j0 = qt * 64 + qrow + g;
    const int j1 = j0 + 8;
    const int jc0 = (j0 < nv) ? j0 : nv - 1;
    const int jc1 = (j1 < nv) ? j1 : nv - 1;
    const __half* Qg0 = qkvh + (tokbase + jc0) * QKVC + h * HD;
    const __half* Qg1 = qkvh + (tokbase + jc1) * QKVC + h * HD;
    uint32_t qf[8][4];
#pragma unroll
    for (int kc = 0; kc < 8; kc++) {
        qf[kc][0] = *(const uint32_t*)(Qg0 + kc * 16 + 2 * q);
        qf[kc][1] = *(const uint32_t*)(Qg1 + kc * 16 + 2 * q);
        qf[kc][2] = *(const uint32_t*)(Qg0 + kc * 16 + 8 + 2 * q);
        qf[kc][3] = *(const uint32_t*)(Qg1 + kc * 16 + 8 + 2 * q);
    }

    __half* pwarp = hsm + POH + (16 * w) * PROW;
    float* svb = (float*)(smc + SVB);

    float o[16][4];
#pragma unroll
    for (int nf = 0; nf < 16; nf++)
#pragma unroll
        for (int r = 0; r < 4; r++) o[nf][r] = 0.f;
    float m0p = -INFINITY, m1p = -INFINITY, l0 = 0.f, l1 = 0.f;
    const float scale = 0.08838834764831843f;

    const __half* KBbase = qkvh + tokbase * QKVC + DIMC + kvh * HD;

#pragma unroll
    for (int s = 0; s < 2; s++) {
        if (s < ntile) {
            ld_kv_c(smb + s * STH * 2, KBbase, s, t);
            if (t < 64) svb[s * 64 + t] = (s * 64 + t < nv) ? 0.f : NEGF;
        }
        CP_COMMIT();
    }

    const uint32_t lrow = (uint32_t)(lane & 15);
    const uint32_t lhi  = (uint32_t)(lane >> 4) * 8u;

    for (int kt = 0; kt < ntile; kt++) {
        CP_WAIT(1);
        __syncthreads();

        const uint32_t ksb = smb + (kt & 1) * STH * 2;
        const uint32_t vsb = ksb + KTH * 2;
        const float* svp = svb + (kt & 1) * 64;

        float c8[8][4];
#pragma unroll
        for (int f = 0; f < 8; f++)
#pragma unroll
            for (int r = 0; r < 4; r++) c8[f][r] = 0.f;

        const uint32_t kfB = ksb + (lrow * AKROW + lhi) * 2;
#pragma unroll
        for (int kc = 0; kc < 8; kc++) {
#pragma unroll
            for (int fb = 0; fb < 4; fb++) {
                uint32_t r[4];
                ldsm4(r, kfB + (uint32_t)(fb * 16 * AKROW * 2 + kc * 32));
                mma_f16(c8[2 * fb],     qf[kc][0], qf[kc][1], qf[kc][2], qf[kc][3], r[0], r[2]);
                mma_f16(c8[2 * fb + 1], qf[kc][0], qf[kc][1], qf[kc][2], qf[kc][3], r[1], r[3]);
            }
        }

        float rmx0 = -INFINITY, rmx1 = -INFINITY;
#pragma unroll
        for (int f = 0; f < 8; f++) {
            float a0 = svp[8 * f + 2 * q], a1 = svp[8 * f + 2 * q + 1];
            c8[f][0] = c8[f][0] * scale + a0;
            c8[f][1] = c8[f][1] * scale + a1;
            c8[f][2] = c8[f][2] * scale + a0;
            c8[f][3] = c8[f][3] * scale + a1;
            rmx0 = fmaxf(rmx0, fmaxf(c8[f][0], c8[f][1]));
            rmx1 = fmaxf(rmx1, fmaxf(c8[f][2], c8[f][3]));
        }
        rmx0 = fmaxf(rmx0, __shfl_xor_sync(0xffffffffu, rmx0, 1));
        rmx0 = fmaxf(rmx0, __shfl_xor_sync(0xffffffffu, rmx0, 2));
        rmx1 = fmaxf(rmx1, __shfl_xor_sync(0xffffffffu, rmx1, 1));
        rmx1 = fmaxf(rmx1, __shfl_xor_sync(0xffffffffu, rmx1, 2));

        float mn0 = fmaxf(m0p, rmx0), mn1 = fmaxf(m1p, rmx1);
        float al0 = __expf(m0p - mn0), al1 = __expf(m1p - mn1);
        m0p = mn0; m1p = mn1;

        float ps0 = 0.f, ps1 = 0.f;
#pragma unroll
        for (int f = 0; f < 8; f++) {
            float p0 = __expf(c8[f][0] - mn0);
            float p1 = __expf(c8[f][1] - mn0);
            float p2 = __expf(c8[f][2] - mn1);
            float p3 = __expf(c8[f][3] - mn1);
            ps0 += p0 + p1; ps1 += p2 + p3;
            *(__half2*)(pwarp + g * PROW + f * 8 + 2 * q) = __floats2half2_rn(p0, p1);
            *(__half2*)(pwarp + (g + 8) * PROW + f * 8 + 2 * q) = __floats2half2_rn(p2, p3);
        }
        ps0 += __shfl_xor_sync(0xffffffffu, ps0, 1);
        ps0 += __shfl_xor_sync(0xffffffffu, ps0, 2);
        ps1 += __shfl_xor_sync(0xffffffffu, ps1, 1);
        ps1 += __shfl_xor_sync(0xffffffffu, ps1, 2);
        l0 = l0 * al0 + ps0;
        l1 = l1 * al1 + ps1;

#pragma unroll
        for (int nf = 0; nf < 16; nf++) {
            o[nf][0] *= al0; o[nf][1] *= al0;
            o[nf][2] *= al1; o[nf][3] *= al1;
        }
        __syncwarp();

        const uint32_t vfB = vsb + (lrow * AKROW + lhi) * 2;
#pragma unroll
        for (int kc = 0; kc < 4; kc++) {
            uint32_t a0 = *(const uint32_t*)(pwarp + g * PROW + kc * 16 + 2 * q);
            uint32_t a1 = *(const uint32_t*)(pwarp + (g + 8) * PROW + kc * 16 + 2 * q);
            uint32_t a2 = *(const uint32_t*)(pwarp + g * PROW + kc * 16 + 8 + 2 * q);
            uint32_t a3 = *(const uint32_t*)(pwarp + (g + 8) * PROW + kc * 16 + 8 + 2 * q);
#pragma unroll
            for (int db = 0; db < 8; db++) {
                uint32_t r[4];
                ldsm4t(r, vfB + (uint32_t)(kc * 16 * AKROW * 2 + db * 32));
                mma_f16(o[2 * db],     a0, a1, a2, a3, r[0], r[1]);
                mma_f16(o[2 * db + 1], a0, a1, a2, a3, r[2], r[3]);
            }
        }

        __syncthreads();
        const int pf = kt + 2;
        if (pf < ntile) {
            ld_kv_c(smb + (pf & 1) * STH * 2, KBbase, pf, t);
            if (t < 64) svb[(pf & 1) * 64 + t] = (pf * 64 + t < nv) ? 0.f : NEGF;
        }
        CP_COMMIT();
    }

    if (j0 < nv) {
        const float f0 = 1.f / l0;
        __half* o0 = outp + (tokbase + j0) * DIMC + h * HD;
#pragma unroll
        for (int nf = 0; nf < 16; nf++)
            *(__half2*)(o0 + nf * 8 + 2 * q) = __floats2half2_rn(o[nf][0] * f0, o[nf][1] * f0);
    }
    if (j1 < nv) {
        const float f1 = 1.f / l1;
        __half* o1 = outp + (tokbase + j1) * DIMC + h * HD;
#pragma unroll
        for (int nf = 0; nf < 16; nf++)
            *(__half2*)(o1 + nf * 8 + 2 * q) = __floats2half2_rn(o[nf][2] * f1, o[nf][3] * f1);
    }
}

// ---------------------------------------------------------------------------
extern "C" void kernel_launch(void* const* d_in, const int* in_sizes, int n_in,
                              void* d_out, int out_size)
{
    const float* x    = (const float*)d_in[0];
    const float* wqkv = (const float*)d_in[1];
    const float* wo   = (const float*)d_in[2];
    const float* qw   = (const float*)d_in[3];
    const float* kw   = (const float*)d_in[4];
    const float* fc   = (const float*)d_in[5];
    const float* fs   = (const float*)d_in[6];
    const unsigned char* visraw = (const unsigned char*)d_in[7];
    float* out = (float*)d_out;

    __half *qkvh, *attnh, *xh, *wqh, *woh;
    int *vidx, *nvis;
    cudaGetSymbolAddress((void**)&qkvh, g_qkvh);
    cudaGetSymbolAddress((void**)&attnh, g_attnh);
    cudaGetSymbolAddress((void**)&xh, g_xh);
    cudaGetSymbolAddress((void**)&wqh, g_wqh);
    cudaGetSymbolAddress((void**)&woh, g_woh);
    cudaGetSymbolAddress((void**)&vidx, g_vidx);
    cudaGetSymbolAddress((void**)&nvis, g_nvis);

    // 0) Prep: mask canonicalize+compact; fused fp16 conversions; masked zero
    prep_mask<<<BB, 1024>>>(visraw);
    cvt_all<<<2048, 256>>>((const float2*)x, (const float2*)wqkv, (const float2*)wo,
                           (__half2*)xh, (__half2*)wqh, (__half2*)woh);
    zero_inv<<<1024, 256>>>((float4*)out);

    // 1) QKV projection over visible rows + fused RMSNorm/RoPE -> compacted qkvh
    cudaFuncSetAttribute(gemm_h<1>, cudaFuncAttributeMaxDynamicSharedMemorySize, HGEMM_SMEM);
    gemm_h<1><<<dim3(QKVC / 128, BB * 16), 256, HGEMM_SMEM>>>(
        xh, wqh, nullptr, qkvh, qw, kw, fc, fs, vidx, nvis, QKVC, DIMC);

    // 2) Attention over compacted rows -> compacted attnh
    cudaFuncSetAttribute(attn_h, cudaFuncAttributeMaxDynamicSharedMemorySize, ATTH_SMEM);
    attn_h<<<dim3(SS / 64, NH / 2, BB), 256, ATTH_SMEM>>>(qkvh, nvis, attnh);

    // 3) Output projection over visible rows -> scattered fp32 out
    cudaFuncSetAttribute(gemm_h<0>, cudaFuncAttributeMaxDynamicSharedMemorySize, HGEMM_SMEM);
    gemm_h<0><<<dim3(DIMC / 128, BB * 16), 256, HGEMM_SMEM>>>(
        attnh, woh, out, nullptr, nullptr, nullptr, nullptr, nullptr,
        vidx, nvis, DIMC, DIMC);
}